// round 8
// baseline (speedup 1.0000x reference)
#include <cuda_runtime.h>
#include <cuda_bf16.h>
#include <cstdint>

// Problem constants
#define Bn 8
#define Nn 16384
#define Cc 4
#define Gg 128          // NUM_GROUPS
#define GS 32           // GROUP_SIZE
#define UK 128          // UPSCALE_K
#define CLU 4           // cluster size for FPS
#define FT 1024         // threads per CTA (fps + bin)
#define PPC (Nn / CLU)  // 4096 points per FPS CTA
#define FPAIR 2         // packed pairs per thread
#define NSLOT (CLU * 32)   // 128 winner slots per buffer
#define GQ_T 128        // group kernel threads
#define NCELL 1000      // 10x10x10 grid

typedef unsigned long long u64t;

__device__ __forceinline__ float NEG_INF() { return __int_as_float(0xff800000); }
__device__ __forceinline__ float POS_INF() { return __int_as_float(0x7f800000); }
#define RADIUS_F 0.1f
#define R2_F 0.01f                  // f32(0.01)
#define THR_F 0.0036f               // f32((2*0.1*0.3)^2)

// Output layout: groups | centers | mask
#define OUT_GROUPS 0
#define OUT_CENTERS (Bn * Gg * GS * Cc)          // 131072
#define OUT_MASK (OUT_CENTERS + Bn * Gg * 3)     // 134144

__device__ float  g_centers[Bn * Gg * 3];
__device__ int    g_retain[Bn * Gg];
__device__ int    g_glen[Bn];
__device__ int    g_cellStart[Bn * (NCELL + 1)];
__device__ float4 g_bpts[Bn * Nn];
__device__ int    g_bidx[Bn * Nn];

// ---- f32x2 packed helpers (sm_100+) ----
__device__ __forceinline__ u64t pk2(float lo, float hi) {
    u64t r; asm("mov.b64 %0, {%1, %2};" : "=l"(r) : "f"(lo), "f"(hi)); return r;
}
__device__ __forceinline__ float plo(u64t v) { return __uint_as_float((unsigned)v); }
__device__ __forceinline__ float phi(u64t v) { return __uint_as_float((unsigned)(v >> 32)); }
__device__ __forceinline__ u64t add2(u64t a, u64t b) {
    u64t r; asm("add.rn.f32x2 %0, %1, %2;" : "=l"(r) : "l"(a), "l"(b)); return r;
}
__device__ __forceinline__ u64t mul2(u64t a, u64t b) {
    u64t r; asm("mul.rn.f32x2 %0, %1, %2;" : "=l"(r) : "l"(a), "l"(b)); return r;
}
__device__ __forceinline__ u64t fma2(u64t a, u64t b, u64t c) {
    u64t r; asm("fma.rn.f32x2 %0, %1, %2, %3;" : "=l"(r) : "l"(a), "l"(b), "l"(c)); return r;
}

// ---- cluster helpers ----
__device__ __forceinline__ uint32_t smem_u32(const void* p) {
    uint32_t a;
    asm("{ .reg .u64 t; cvta.to.shared.u64 t, %1; cvt.u32.u64 %0, t; }" : "=r"(a) : "l"(p));
    return a;
}
__device__ __forceinline__ void st_clu_u64(uint32_t laddr, uint32_t rank, u64t v) {
    uint32_t ra;
    asm("mapa.shared::cluster.u32 %0, %1, %2;" : "=r"(ra) : "r"(laddr), "r"(rank));
    asm volatile("st.shared::cluster.u64 [%0], %1;" :: "r"(ra), "l"(v) : "memory");
}
__device__ __forceinline__ void st_clu_f32(uint32_t laddr, uint32_t rank, float v) {
    uint32_t ra;
    asm("mapa.shared::cluster.u32 %0, %1, %2;" : "=r"(ra) : "r"(laddr), "r"(rank));
    asm volatile("st.shared::cluster.f32 [%0], %1;" :: "r"(ra), "f"(v) : "memory");
}
__device__ __forceinline__ void mbar_init(uint32_t addr, uint32_t count) {
    asm volatile("mbarrier.init.shared.b64 [%0], %1;" :: "r"(addr), "r"(count) : "memory");
}
__device__ __forceinline__ void mbar_arrive_rel_cluster(uint32_t laddr, uint32_t rank) {
    uint32_t ra;
    asm("mapa.shared::cluster.u32 %0, %1, %2;" : "=r"(ra) : "r"(laddr), "r"(rank));
    asm volatile("mbarrier.arrive.release.cluster.shared::cluster.b64 _, [%0];"
                 :: "r"(ra) : "memory");
}
__device__ __forceinline__ void mbar_wait_acq_cluster(uint32_t addr, uint32_t parity) {
    asm volatile(
        "{\n\t.reg .pred P;\n\t"
        "WL_%=:\n\t"
        "mbarrier.try_wait.parity.acquire.cluster.shared::cta.b64 P, [%0], %1, 0x989680;\n\t"
        "@P bra.uni WD_%=;\n\t"
        "bra.uni WL_%=;\n\t"
        "WD_%=:\n\t}"
        :: "r"(addr), "r"(parity) : "memory");
}
__device__ __forceinline__ void cluster_sync_() {
    asm volatile("barrier.cluster.arrive.aligned;" ::: "memory");
    asm volatile("barrier.cluster.wait.aligned;" ::: "memory");
}

__device__ __forceinline__ int cell_of(float x, float y, float z) {
    int cx = (int)(x * 10.0f); cx = cx < 0 ? 0 : (cx > 9 ? 9 : cx);
    int cy = (int)(y * 10.0f); cy = cy < 0 ? 0 : (cy > 9 ? 9 : cy);
    int cz = (int)(z * 10.0f); cz = cz < 0 ? 0 : (cz > 9 ? 9 : cz);
    return (cz * 10 + cy) * 10 + cx;
}

// ---------------------------------------------------------------------------
// Kernel 1: blocks [0, Bn*CLU): cluster-parallel FPS (single-stage reduction)
//           blocks [Bn*CLU, Bn*CLU+Bn): per-batch grid binning (overlapped)
// ---------------------------------------------------------------------------
__global__ __launch_bounds__(FT) __cluster_dims__(CLU, 1, 1)
void fps_kernel(const float4* __restrict__ pts,
                const int* __restrict__ lengths,
                float* __restrict__ out) {
    const int bid = blockIdx.x;
    const int t = threadIdx.x;

    if (bid >= Bn * CLU) {
        // ---------------- binning path ----------------
        const int b = bid - Bn * CLU;
        const float4* __restrict__ p = pts + (size_t)b * Nn;
        __shared__ int s_cnt[NCELL];
        __shared__ int s_scan[FT];

        if (t < NCELL) s_cnt[t] = 0;
        __syncthreads();

        int cellr[16];
        #pragma unroll
        for (int k = 0; k < 16; k++) {
            const int i = t + k * FT;
            float4 v = __ldg(p + i);
            const int c = cell_of(v.x, v.y, v.z);
            cellr[k] = c;
            atomicAdd(&s_cnt[c], 1);
        }
        __syncthreads();

        const int myc = (t < NCELL) ? s_cnt[t] : 0;
        s_scan[t] = myc;
        __syncthreads();
        #pragma unroll
        for (int off = 1; off < FT; off <<= 1) {
            int x = (t >= off) ? s_scan[t - off] : 0;
            __syncthreads();
            s_scan[t] += x;
            __syncthreads();
        }
        const int excl = s_scan[t] - myc;
        if (t < NCELL) g_cellStart[b * (NCELL + 1) + t] = excl;
        if (t == 0) g_cellStart[b * (NCELL + 1) + NCELL] = Nn;
        __syncthreads();
        if (t < NCELL) s_cnt[t] = excl;      // running cursors
        __syncthreads();

        #pragma unroll
        for (int k = 0; k < 16; k++) {
            const int i = t + k * FT;
            const int pos = atomicAdd(&s_cnt[cellr[k]], 1);
            g_bpts[(size_t)b * Nn + pos] = __ldg(p + i);
            g_bidx[(size_t)b * Nn + pos] = i;
        }
        return;
    }

    // ---------------- FPS path ----------------
    const int b = bid / CLU;
    const int r = bid % CLU;
    const float4* __restrict__ p = pts + (size_t)b * Nn;
    const int len = lengths[b];
    const int lane = t & 31, warp = t >> 5;
    const int base = r * PPC;

    __shared__ __align__(16) u64t  s_skey[2][NSLOT];
    __shared__ __align__(16) u64t  s_sxy[2][NSLOT];
    __shared__ float s_sz[2][NSLOT];
    __shared__ __align__(8) unsigned char s_bar[2][8];
    __shared__ float s_centers[Gg * 3];

    const uint32_t a_skey = smem_u32(&s_skey[0][0]);
    const uint32_t a_sxy  = smem_u32(&s_sxy[0][0]);
    const uint32_t a_sz   = smem_u32(&s_sz[0][0]);
    const uint32_t a_bar  = smem_u32(&s_bar[0][0]);

    if (t == 0) {
        mbar_init(a_bar, NSLOT);        // 32 warps x 4 ranks arrivals per phase
        mbar_init(a_bar + 8, NSLOT);
        if (r == 0) g_glen[b] = 0;
    }

    u64t Xp[FPAIR], Yp[FPAIR], Zp[FPAIR];
    float Mlo[FPAIR], Mhi[FPAIR];
    #pragma unroll
    for (int j = 0; j < FPAIR; j++) {
        const int i0 = base + t + (2 * j) * FT;
        const int i1 = i0 + FT;
        float4 a = __ldg(p + i0);
        float4 c = __ldg(p + i1);
        Xp[j] = pk2(a.x, c.x);
        Yp[j] = pk2(a.y, c.y);
        Zp[j] = pk2(a.z, c.z);
        Mlo[j] = (i0 < len) ? POS_INF() : NEG_INF();
        Mhi[j] = (i1 < len) ? POS_INF() : NEG_INF();
    }

    float4 c0 = __ldg(p);
    float cx = c0.x, cy = c0.y, cz = c0.z;
    if (r == 0 && t == 0) {
        s_centers[0] = cx; s_centers[1] = cy; s_centers[2] = cz;
    }

    // barriers must be cluster-visible before any remote arrive
    __syncthreads();
    cluster_sync_();

    unsigned ph0 = 0, ph1 = 0;

    for (int s = 1; s < Gg; s++) {
        const int q = s & 1;
        const u64t ncx = pk2(-cx, -cx);
        const u64t ncy = pk2(-cy, -cy);
        const u64t ncz = pk2(-cz, -cz);

        #pragma unroll
        for (int j = 0; j < FPAIR; j++) {
            u64t dx = add2(Xp[j], ncx);
            u64t dy = add2(Yp[j], ncy);
            u64t dz = add2(Zp[j], ncz);
            u64t d = mul2(dx, dx);
            d = fma2(dy, dy, d);
            d = fma2(dz, dz, d);
            Mlo[j] = fminf(Mlo[j], plo(d));
            Mhi[j] = fminf(Mhi[j], phi(d));
        }

        float bv = fmaxf(fmaxf(Mlo[0], Mhi[0]), fmaxf(Mlo[1], Mhi[1]));
        const int bb = __float_as_int(bv);
        const int wmax = __reduce_max_sync(0xffffffffu, bb);

        int bk = 3;
        if (Mlo[1] == bv) bk = 2;
        if (Mhi[0] == bv) bk = 1;
        if (Mlo[0] == bv) bk = 0;

        unsigned gl = (bb == wmax) ? ((unsigned)(bk << 10) + (unsigned)t) : 0xffffffffu;
        const unsigned gmin = __reduce_min_sync(0xffffffffu, gl);

        const unsigned tv = (wmax >= 0) ? ((unsigned)wmax | 0x80000000u) : ~(unsigned)wmax;
        const u64t wkey = ((u64t)tv << 32) | (u64t)(0xffffffffu - (unsigned)(base + (int)gmin));

        // winner lane pushes this warp's {key, coords} to ALL ranks' slot (r*32+warp)
        if (gl == gmin) {
            const int jj = bk >> 1;
            const bool hi = bk & 1;
            const float sx = hi ? phi(Xp[jj]) : plo(Xp[jj]);
            const float sy = hi ? phi(Yp[jj]) : plo(Yp[jj]);
            const float sz = hi ? phi(Zp[jj]) : plo(Zp[jj]);
            const u64t xy = pk2(sx, sy);
            const uint32_t slot = (uint32_t)(q * NSLOT + r * 32 + warp);
            #pragma unroll
            for (int i = 0; i < CLU; i++) {
                st_clu_u64(a_skey + slot * 8, (uint32_t)i, wkey);
                st_clu_u64(a_sxy + slot * 8, (uint32_t)i, xy);
                st_clu_f32(a_sz + slot * 4, (uint32_t)i, sz);
                mbar_arrive_rel_cluster(a_bar + (uint32_t)q * 8, (uint32_t)i);
            }
        }

        // every warp waits for all 128 pushes, then combines independently
        if (q) { mbar_wait_acq_cluster(a_bar + 8, ph1); ph1 ^= 1u; }
        else   { mbar_wait_acq_cluster(a_bar, ph0); ph0 ^= 1u; }

        // combine 128 keys: 4 per lane
        const u64t* kb = &s_skey[q][0];
        const ulonglong2 ka = *(const ulonglong2*)(kb + lane * 4);
        const ulonglong2 kc = *(const ulonglong2*)(kb + lane * 4 + 2);
        u64t lm = ka.x > ka.y ? ka.x : ka.y;
        const u64t lm2 = kc.x > kc.y ? kc.x : kc.y;
        lm = lm > lm2 ? lm : lm2;
        const unsigned hm = __reduce_max_sync(0xffffffffu, (unsigned)(lm >> 32));
        const unsigned lw = ((unsigned)(lm >> 32) == hm) ? (unsigned)lm : 0u;
        const unsigned lmx = __reduce_max_sync(0xffffffffu, lw);
        const u64t m = ((u64t)hm << 32) | (u64t)lmx;

        int slot = -1;
        if (ka.x == m) slot = lane * 4 + 0;
        else if (ka.y == m) slot = lane * 4 + 1;
        else if (kc.x == m) slot = lane * 4 + 2;
        else if (kc.y == m) slot = lane * 4 + 3;
        const unsigned ball = __ballot_sync(0xffffffffu, slot >= 0);
        const int srcl = __ffs(ball) - 1;
        slot = __shfl_sync(0xffffffffu, slot, srcl);

        const u64t wxy = s_sxy[q][slot];
        cx = plo(wxy); cy = phi(wxy); cz = s_sz[q][slot];

        if (r == 0 && t == 0) {
            s_centers[s * 3 + 0] = cx;
            s_centers[s * 3 + 1] = cy;
            s_centers[s * 3 + 2] = cz;
        }
    }

    cluster_sync_();
    if (r != 0) return;
    __syncthreads();

    for (int i = t; i < Gg * 3; i += FT) {
        float v = s_centers[i];
        g_centers[(size_t)b * Gg * 3 + i] = v;
        out[OUT_CENTERS + (size_t)b * Gg * 3 + i] = v;
    }

    if (t < 32) {
        float kx[4], ky[4], kz[4];
        bool kp[4];
        #pragma unroll
        for (int qq = 0; qq < 4; qq++) {
            const int i = lane + qq * 32;
            kx[qq] = s_centers[i * 3 + 0];
            ky[qq] = s_centers[i * 3 + 1];
            kz[qq] = s_centers[i * 3 + 2];
            kp[qq] = false;
        }
        for (int j = 0; j < Gg; j++) {
            const float jx = s_centers[j * 3 + 0];
            const float jy = s_centers[j * 3 + 1];
            const float jz = s_centers[j * 3 + 2];
            bool conflict = false;
            #pragma unroll
            for (int qq = 0; qq < 4; qq++) {
                float dx = kx[qq] - jx, dy = ky[qq] - jy, dz = kz[qq] - jz;
                float d2 = dx * dx + dy * dy + dz * dz;
                if (kp[qq] && d2 < THR_F) conflict = true;
            }
            conflict = __any_sync(0xffffffffu, conflict);
            if (!conflict && lane == (j & 31)) kp[j >> 5] = true;
        }
        #pragma unroll
        for (int qq = 0; qq < 4; qq++) g_retain[b * Gg + lane + qq * 32] = kp[qq] ? 1 : 0;
    }
}

// ---------------------------------------------------------------------------
// Kernel 2: per-(group,batch) grid-culled ball query + top-32 + output
// ---------------------------------------------------------------------------
__global__ __launch_bounds__(GQ_T) void group_kernel(const float4* __restrict__ pts,
                                                     const int* __restrict__ lengths,
                                                     float* __restrict__ out) {
    const int g = blockIdx.x, b = blockIdx.y;
    const float* __restrict__ pf = (const float*)(pts + (size_t)b * Nn);
    const int t = threadIdx.x;
    const int len = lengths[b];

    const float cx = g_centers[((size_t)b * Gg + g) * 3 + 0];
    const float cy = g_centers[((size_t)b * Gg + g) * 3 + 1];
    const float cz = g_centers[((size_t)b * Gg + g) * 3 + 2];
    const int retain = g_retain[b * Gg + g];

    __shared__ int  s_segS[64];
    __shared__ int  s_segE[64];
    __shared__ u64t s_keys[256];
    __shared__ int  s_n;
    __shared__ int  s_tidx[GS];

    if (t == 0) s_n = 0;
    s_keys[t] = 0ull;
    s_keys[t + GQ_T] = 0ull;

    int lox = (int)floorf((cx - RADIUS_F) * 10.0f - 1e-4f); lox = lox < 0 ? 0 : lox;
    int hix = (int)floorf((cx + RADIUS_F) * 10.0f + 1e-4f); hix = hix > 9 ? 9 : hix;
    int loy = (int)floorf((cy - RADIUS_F) * 10.0f - 1e-4f); loy = loy < 0 ? 0 : loy;
    int hiy = (int)floorf((cy + RADIUS_F) * 10.0f + 1e-4f); hiy = hiy > 9 ? 9 : hiy;
    int loz = (int)floorf((cz - RADIUS_F) * 10.0f - 1e-4f); loz = loz < 0 ? 0 : loz;
    int hiz = (int)floorf((cz + RADIUS_F) * 10.0f + 1e-4f); hiz = hiz > 9 ? 9 : hiz;
    const int nx = hix - lox + 1, ny = hiy - loy + 1, nz = hiz - loz + 1;
    int nTot = retain ? (nx * ny * nz) : 0;

    int segCnt = 0;
    if (t < 64 && t < nTot) {
        const int ix = t % nx;
        const int iy = (t / nx) % ny;
        const int iz = t / (nx * ny);
        const int cell = ((loz + iz) * 10 + (loy + iy)) * 10 + (lox + ix);
        const int st = g_cellStart[b * (NCELL + 1) + cell];
        const int en = g_cellStart[b * (NCELL + 1) + cell + 1];
        s_segS[t] = st;
        segCnt = en - st;
    }
    if (t < 64) s_segE[t] = segCnt;
    __syncthreads();
    #pragma unroll
    for (int off = 1; off < 64; off <<= 1) {
        int x = (t >= off && t < 64) ? s_segE[t - off] : 0;
        __syncthreads();
        if (t < 64) s_segE[t] += x;
        __syncthreads();
    }
    const int C = (nTot > 0) ? s_segE[nTot - 1] : 0;
    if (t < 64) s_segE[t] -= segCnt;
    __syncthreads();

    const float4* __restrict__ bp = g_bpts + (size_t)b * Nn;
    const int* __restrict__ bi = g_bidx + (size_t)b * Nn;
    for (int pos = t; pos < C; pos += GQ_T) {
        int lo = 0, hi2 = nTot - 1;
        while (lo < hi2) {
            const int mid = (lo + hi2 + 1) >> 1;
            if (s_segE[mid] <= pos) lo = mid; else hi2 = mid - 1;
        }
        const int gp = s_segS[lo] + (pos - s_segE[lo]);
        float4 v = __ldg(bp + gp);
        const int idx = __ldg(bi + gp);
        const float dx = v.x - cx, dy = v.y - cy, dz = v.z - cz;
        const float d2 = dx * dx + dy * dy + dz * dz;
        if (d2 <= R2_F && idx < len) {
            const unsigned eb = __float_as_uint(v.w);
            const unsigned vb = (eb & 0x80000000u) ? ~eb : (eb | 0x80000000u);
            const int slot = atomicAdd(&s_n, 1);
            if (slot < 256)
                s_keys[slot] = ((u64t)vb << 32) | (u64t)(0xffffffffu - (unsigned)idx);
        }
    }
    __syncthreads();

    const int total = s_n;

    // cold path (never on this dataset): order by index, keep first UK
    if (total > UK) {
        #pragma unroll
        for (int k = 2; k <= 256; k <<= 1) {
            #pragma unroll
            for (int j = k >> 1; j > 0; j >>= 1) {
                #pragma unroll
                for (int e = 0; e < 2; e++) {
                    const int i = t + e * GQ_T;
                    const int l = i ^ j;
                    if (l > i) {
                        const u64t a = s_keys[i], c = s_keys[l];
                        const unsigned la = (unsigned)a, lc = (unsigned)c;
                        const bool up = ((i & k) == 0);
                        if (up ? (la < lc) : (la > lc)) { s_keys[i] = c; s_keys[l] = a; }
                    }
                }
                __syncthreads();
            }
        }
    }
    __syncthreads();

    const int numEff = total < UK ? total : UK;

    if (t < 32) {
        u64t key[4];
        #pragma unroll
        for (int rr = 0; rr < 4; rr++) {
            const int slot = rr * 32 + t;
            key[rr] = (slot < numEff) ? s_keys[slot] : 0ull;
        }
        #pragma unroll
        for (int k = 2; k <= 128; k <<= 1) {
            #pragma unroll
            for (int j = k >> 1; j > 0; j >>= 1) {
                if (j >= 32) {
                    const int rj = j >> 5;
                    #pragma unroll
                    for (int rr = 0; rr < 4; rr++) {
                        const int pr = rr ^ rj;
                        if (pr > rr) {
                            const int e = rr * 32 + t;
                            const bool dsc = ((e & k) == 0);
                            u64t a = key[rr], c = key[pr];
                            u64t mx = a > c ? a : c;
                            u64t mn = a > c ? c : a;
                            key[rr] = dsc ? mx : mn;
                            key[pr] = dsc ? mn : mx;
                        }
                    }
                } else {
                    #pragma unroll
                    for (int rr = 0; rr < 4; rr++) {
                        const int e = rr * 32 + t;
                        u64t o = __shfl_xor_sync(0xffffffffu, key[rr], j);
                        const bool low = ((t & j) == 0);
                        const bool dsc = ((e & k) == 0);
                        const bool takeMax = (dsc == low);
                        u64t mx = key[rr] > o ? key[rr] : o;
                        u64t mn = key[rr] > o ? o : key[rr];
                        key[rr] = takeMax ? mx : mn;
                    }
                }
            }
        }
        const u64t k0 = key[0];
        const int idx = (int)(0xffffffffu - (unsigned)k0);
        s_tidx[t] = ((unsigned)(k0 >> 32) >= 0x80000000u) ? idx : -1;
    }
    __syncthreads();

    {
        const int rr = t >> 2, c = t & 3;
        const int ti = s_tidx[rr];
        const int fi = (ti == -1) ? s_tidx[0] : ti;
        float val = (fi == -1) ? 0.0f : pf[(size_t)fi * 4 + c];
        if (c < 3) {
            const float cc = (c == 0) ? cx : (c == 1) ? cy : cz;
            val -= cc;
        }
        val = __fdiv_rn(val, RADIUS_F);
        out[OUT_GROUPS + ((((size_t)b * Gg + g) * GS) + rr) * Cc + c] = val;
    }
    if (t == 0 && total >= GS) atomicAdd(&g_glen[b], 1);
}

// ---------------------------------------------------------------------------
// Kernel 3: embedding mask
// ---------------------------------------------------------------------------
__global__ void mask_kernel(float* __restrict__ out) {
    const int i = blockIdx.x * blockDim.x + threadIdx.x;
    if (i < Bn * Gg) {
        const int b = i >> 7, g = i & (Gg - 1);
        out[OUT_MASK + i] = (g < g_glen[b]) ? 1.0f : 0.0f;
    }
}

extern "C" void kernel_launch(void* const* d_in, const int* in_sizes, int n_in,
                              void* d_out, int out_size) {
    const float4* pts = (const float4*)d_in[0];
    const int* lengths = (const int*)d_in[1];
    float* out = (float*)d_out;
    (void)in_sizes; (void)n_in; (void)out_size;

    fps_kernel<<<Bn * CLU + Bn, FT>>>(pts, lengths, out);
    group_kernel<<<dim3(Gg, Bn), GQ_T>>>(pts, lengths, out);
    mask_kernel<<<(Bn * Gg + 255) / 256, 256>>>(out);
}

// round 9
// speedup vs baseline: 1.9240x; 1.9240x over previous
#include <cuda_runtime.h>
#include <cuda_bf16.h>
#include <cstdint>

// Problem constants
#define Bn 8
#define Nn 16384
#define Cc 4
#define Gg 128          // NUM_GROUPS
#define GS 32           // GROUP_SIZE
#define UK 128          // UPSCALE_K
#define CLU 4           // cluster size for FPS
#define FT 1024         // threads per CTA (fps + bin)
#define PPC (Nn / CLU)  // 4096 points per FPS CTA
#define FPAIR 2         // packed pairs per thread
#define GQ_T 128        // group kernel threads
#define NCELL 1000      // 10x10x10 grid

typedef unsigned long long u64t;

__device__ __forceinline__ float NEG_INF() { return __int_as_float(0xff800000); }
__device__ __forceinline__ float POS_INF() { return __int_as_float(0x7f800000); }
#define RADIUS_F 0.1f
#define R2_F 0.01f                  // f32(0.01)
#define THR_F 0.0036f               // f32((2*0.1*0.3)^2)

// Output layout: groups | centers | mask
#define OUT_GROUPS 0
#define OUT_CENTERS (Bn * Gg * GS * Cc)          // 131072
#define OUT_MASK (OUT_CENTERS + Bn * Gg * 3)     // 134144

__device__ float  g_centers[Bn * Gg * 3];
__device__ int    g_retain[Bn * Gg];
__device__ int    g_glen[Bn];
__device__ int    g_cellStart[Bn * (NCELL + 1)];
__device__ float4 g_bpts[Bn * Nn];
__device__ int    g_bidx[Bn * Nn];

// ---- f32x2 packed helpers (sm_100+) ----
__device__ __forceinline__ u64t pk2(float lo, float hi) {
    u64t r; asm("mov.b64 %0, {%1, %2};" : "=l"(r) : "f"(lo), "f"(hi)); return r;
}
__device__ __forceinline__ float plo(u64t v) { return __uint_as_float((unsigned)v); }
__device__ __forceinline__ float phi(u64t v) { return __uint_as_float((unsigned)(v >> 32)); }
__device__ __forceinline__ u64t add2(u64t a, u64t b) {
    u64t r; asm("add.rn.f32x2 %0, %1, %2;" : "=l"(r) : "l"(a), "l"(b)); return r;
}
__device__ __forceinline__ u64t mul2(u64t a, u64t b) {
    u64t r; asm("mul.rn.f32x2 %0, %1, %2;" : "=l"(r) : "l"(a), "l"(b)); return r;
}
__device__ __forceinline__ u64t fma2(u64t a, u64t b, u64t c) {
    u64t r; asm("fma.rn.f32x2 %0, %1, %2, %3;" : "=l"(r) : "l"(a), "l"(b), "l"(c)); return r;
}

// ---- cluster helpers ----
__device__ __forceinline__ uint32_t smem_u32(const void* p) {
    uint32_t a;
    asm("{ .reg .u64 t; cvta.to.shared.u64 t, %1; cvt.u32.u64 %0, t; }" : "=r"(a) : "l"(p));
    return a;
}
__device__ __forceinline__ void st_clu_u64(uint32_t laddr, uint32_t rank, u64t v) {
    uint32_t ra;
    asm("mapa.shared::cluster.u32 %0, %1, %2;" : "=r"(ra) : "r"(laddr), "r"(rank));
    asm volatile("st.shared::cluster.u64 [%0], %1;" :: "r"(ra), "l"(v) : "memory");
}
__device__ __forceinline__ void st_clu_f32(uint32_t laddr, uint32_t rank, float v) {
    uint32_t ra;
    asm("mapa.shared::cluster.u32 %0, %1, %2;" : "=r"(ra) : "r"(laddr), "r"(rank));
    asm volatile("st.shared::cluster.f32 [%0], %1;" :: "r"(ra), "f"(v) : "memory");
}
__device__ __forceinline__ void mbar_init(uint32_t addr, uint32_t count) {
    asm volatile("mbarrier.init.shared.b64 [%0], %1;" :: "r"(addr), "r"(count) : "memory");
}
__device__ __forceinline__ void mbar_arrive_rel_cluster(uint32_t laddr, uint32_t rank) {
    uint32_t ra;
    asm("mapa.shared::cluster.u32 %0, %1, %2;" : "=r"(ra) : "r"(laddr), "r"(rank));
    asm volatile("mbarrier.arrive.release.cluster.shared::cluster.b64 _, [%0];"
                 :: "r"(ra) : "memory");
}
__device__ __forceinline__ void mbar_wait_acq_cluster(uint32_t addr, uint32_t parity) {
    asm volatile(
        "{\n\t.reg .pred P;\n\t"
        "WL_%=:\n\t"
        "mbarrier.try_wait.parity.acquire.cluster.shared::cta.b64 P, [%0], %1, 0x989680;\n\t"
        "@P bra.uni WD_%=;\n\t"
        "bra.uni WL_%=;\n\t"
        "WD_%=:\n\t}"
        :: "r"(addr), "r"(parity) : "memory");
}
__device__ __forceinline__ void cluster_sync_() {
    asm volatile("barrier.cluster.arrive.aligned;" ::: "memory");
    asm volatile("barrier.cluster.wait.aligned;" ::: "memory");
}

__device__ __forceinline__ int cell_of(float x, float y, float z) {
    int cx = (int)(x * 10.0f); cx = cx < 0 ? 0 : (cx > 9 ? 9 : cx);
    int cy = (int)(y * 10.0f); cy = cy < 0 ? 0 : (cy > 9 ? 9 : cy);
    int cz = (int)(z * 10.0f); cz = cz < 0 ? 0 : (cz > 9 ? 9 : cz);
    return (cz * 10 + cy) * 10 + cx;
}

// ---------------------------------------------------------------------------
// Kernel 1: blocks [0, Bn*CLU): cluster-parallel FPS
//           blocks [Bn*CLU, Bn*CLU+Bn): per-batch grid binning (overlapped)
// ---------------------------------------------------------------------------
__global__ __launch_bounds__(FT) __cluster_dims__(CLU, 1, 1)
void fps_kernel(const float4* __restrict__ pts,
                const int* __restrict__ lengths,
                float* __restrict__ out) {
    const int bid = blockIdx.x;
    const int t = threadIdx.x;

    if (bid >= Bn * CLU) {
        // ---------------- binning path ----------------
        const int b = bid - Bn * CLU;
        const float4* __restrict__ p = pts + (size_t)b * Nn;
        __shared__ int s_cnt[NCELL];
        __shared__ int s_scan[FT];

        if (t < NCELL) s_cnt[t] = 0;
        __syncthreads();

        int cellr[16];
        #pragma unroll
        for (int k = 0; k < 16; k++) {
            const int i = t + k * FT;
            float4 v = __ldg(p + i);
            const int c = cell_of(v.x, v.y, v.z);
            cellr[k] = c;
            atomicAdd(&s_cnt[c], 1);
        }
        __syncthreads();

        const int myc = (t < NCELL) ? s_cnt[t] : 0;
        s_scan[t] = myc;
        __syncthreads();
        #pragma unroll
        for (int off = 1; off < FT; off <<= 1) {
            int x = (t >= off) ? s_scan[t - off] : 0;
            __syncthreads();
            s_scan[t] += x;
            __syncthreads();
        }
        const int excl = s_scan[t] - myc;
        if (t < NCELL) g_cellStart[b * (NCELL + 1) + t] = excl;
        if (t == 0) g_cellStart[b * (NCELL + 1) + NCELL] = Nn;
        __syncthreads();
        if (t < NCELL) s_cnt[t] = excl;      // running cursors
        __syncthreads();

        #pragma unroll
        for (int k = 0; k < 16; k++) {
            const int i = t + k * FT;
            const int pos = atomicAdd(&s_cnt[cellr[k]], 1);
            g_bpts[(size_t)b * Nn + pos] = __ldg(p + i);
            g_bidx[(size_t)b * Nn + pos] = i;
        }
        return;
    }

    // ---------------- FPS path ----------------
    const int b = bid / CLU;
    const int r = bid % CLU;
    const float4* __restrict__ p = pts + (size_t)b * Nn;
    const int len = lengths[b];
    const int lane = t & 31, warp = t >> 5;
    const int base = r * PPC;

    __shared__ u64t  s_wk[32];
    __shared__ u64t  s_wxy[32];
    __shared__ float s_wz[32];
    __shared__ __align__(16) u64t  s_skey[2][CLU];
    __shared__ __align__(16) u64t  s_sxy[2][CLU];
    __shared__ float s_sz[2][CLU];
    __shared__ __align__(8) unsigned char s_bar[2][8];
    __shared__ float s_centers[Gg * 3];

    const uint32_t a_skey = smem_u32(&s_skey[0][0]);
    const uint32_t a_sxy  = smem_u32(&s_sxy[0][0]);
    const uint32_t a_sz   = smem_u32(&s_sz[0][0]);
    const uint32_t a_bar  = smem_u32(&s_bar[0][0]);

    if (t == 0) {
        mbar_init(a_bar, CLU);
        mbar_init(a_bar + 8, CLU);
        if (r == 0) g_glen[b] = 0;
    }

    u64t Xp[FPAIR], Yp[FPAIR], Zp[FPAIR];
    float Mlo[FPAIR], Mhi[FPAIR];
    #pragma unroll
    for (int j = 0; j < FPAIR; j++) {
        const int i0 = base + t + (2 * j) * FT;
        const int i1 = i0 + FT;
        float4 a = __ldg(p + i0);
        float4 c = __ldg(p + i1);
        Xp[j] = pk2(a.x, c.x);
        Yp[j] = pk2(a.y, c.y);
        Zp[j] = pk2(a.z, c.z);
        Mlo[j] = (i0 < len) ? POS_INF() : NEG_INF();
        Mhi[j] = (i1 < len) ? POS_INF() : NEG_INF();
    }

    float4 c0 = __ldg(p);
    float cx = c0.x, cy = c0.y, cz = c0.z;
    if (r == 0 && t == 0) {
        s_centers[0] = cx; s_centers[1] = cy; s_centers[2] = cz;
    }

    // barriers must be cluster-visible before any remote arrive
    __syncthreads();
    cluster_sync_();

    unsigned ph0 = 0, ph1 = 0;

    for (int s = 1; s < Gg; s++) {
        const int q = s & 1;
        const u64t ncx = pk2(-cx, -cx);
        const u64t ncy = pk2(-cy, -cy);
        const u64t ncz = pk2(-cz, -cz);

        #pragma unroll
        for (int j = 0; j < FPAIR; j++) {
            u64t dx = add2(Xp[j], ncx);
            u64t dy = add2(Yp[j], ncy);
            u64t dz = add2(Zp[j], ncz);
            u64t d = mul2(dx, dx);
            d = fma2(dy, dy, d);
            d = fma2(dz, dz, d);
            Mlo[j] = fminf(Mlo[j], plo(d));
            Mhi[j] = fminf(Mhi[j], phi(d));
        }

        float bv = fmaxf(fmaxf(Mlo[0], Mhi[0]), fmaxf(Mlo[1], Mhi[1]));
        const int bb = __float_as_int(bv);
        const int wmax = __reduce_max_sync(0xffffffffu, bb);

        int bk = 3;
        if (Mlo[1] == bv) bk = 2;
        if (Mhi[0] == bv) bk = 1;
        if (Mlo[0] == bv) bk = 0;

        unsigned gl = (bb == wmax) ? ((unsigned)(bk << 10) + (unsigned)t) : 0xffffffffu;
        const unsigned gmin = __reduce_min_sync(0xffffffffu, gl);

        const unsigned tv = (wmax >= 0) ? ((unsigned)wmax | 0x80000000u) : ~(unsigned)wmax;
        const u64t wkey = ((u64t)tv << 32) | (u64t)(0xffffffffu - (unsigned)(base + (int)gmin));

        // winner lane writes its own key + coords (no shuffles)
        if (gl == gmin) {
            const int jj = bk >> 1;
            const bool hi = bk & 1;
            const float sx = hi ? phi(Xp[jj]) : plo(Xp[jj]);
            const float sy = hi ? phi(Yp[jj]) : plo(Yp[jj]);
            const float sz = hi ? phi(Zp[jj]) : plo(Zp[jj]);
            s_wk[warp] = wkey;
            s_wxy[warp] = pk2(sx, sy);
            s_wz[warp] = sz;
        }
        __syncthreads();

        if (warp == 0) {
            // combine 32 warp winners via two u32 redux ops
            const u64t k = s_wk[lane];
            u64t xy = s_wxy[lane];
            float z = s_wz[lane];
            const unsigned tvp = (unsigned)(k >> 32);
            const unsigned lowp = (unsigned)k;
            const unsigned tmax = __reduce_max_sync(0xffffffffu, tvp);
            const unsigned lw = (tvp == tmax) ? lowp : 0u;
            const unsigned lmax = __reduce_max_sync(0xffffffffu, lw); // = max(~gidx) = min gidx
            const u64t m = ((u64t)tmax << 32) | (u64t)lmax;
            const unsigned ball = __ballot_sync(0xffffffffu, (tvp == tmax) && (lowp == lmax));
            const int srcw = __ffs(ball) - 1;
            xy = __shfl_sync(0xffffffffu, xy, srcw);
            z = __shfl_sync(0xffffffffu, z, srcw);

            // lanes 0..3 push CTA winner to rank=lane in parallel, then arrive
            if (lane < CLU) {
                const uint32_t off8 = (uint32_t)(q * CLU + r) * 8;
                const uint32_t off4 = (uint32_t)(q * CLU + r) * 4;
                st_clu_u64(a_skey + off8, (uint32_t)lane, m);
                st_clu_u64(a_sxy + off8, (uint32_t)lane, xy);
                st_clu_f32(a_sz + off4, (uint32_t)lane, z);
                mbar_arrive_rel_cluster(a_bar + (uint32_t)q * 8, (uint32_t)lane);
            }
        }

        // ALL warps wait for the 4 rank pushes, then pick winner independently
        if (q) { mbar_wait_acq_cluster(a_bar + 8, ph1); ph1 ^= 1u; }
        else   { mbar_wait_acq_cluster(a_bar, ph0); ph0 ^= 1u; }

        u64t km = s_skey[q][0];
        int w = 0;
        #pragma unroll
        for (int i = 1; i < CLU; i++) {
            u64t ki = s_skey[q][i];
            if (ki > km) { km = ki; w = i; }
        }
        const u64t wxy = s_sxy[q][w];
        cx = plo(wxy); cy = phi(wxy); cz = s_sz[q][w];

        if (r == 0 && t == 0) {
            s_centers[s * 3 + 0] = cx;
            s_centers[s * 3 + 1] = cy;
            s_centers[s * 3 + 2] = cz;
        }
    }

    cluster_sync_();
    if (r != 0) return;
    __syncthreads();

    for (int i = t; i < Gg * 3; i += FT) {
        float v = s_centers[i];
        g_centers[(size_t)b * Gg * 3 + i] = v;
        out[OUT_CENTERS + (size_t)b * Gg * 3 + i] = v;
    }

    if (t < 32) {
        float kx[4], ky[4], kz[4];
        bool kp[4];
        #pragma unroll
        for (int qq = 0; qq < 4; qq++) {
            const int i = lane + qq * 32;
            kx[qq] = s_centers[i * 3 + 0];
            ky[qq] = s_centers[i * 3 + 1];
            kz[qq] = s_centers[i * 3 + 2];
            kp[qq] = false;
        }
        for (int j = 0; j < Gg; j++) {
            const float jx = s_centers[j * 3 + 0];
            const float jy = s_centers[j * 3 + 1];
            const float jz = s_centers[j * 3 + 2];
            bool conflict = false;
            #pragma unroll
            for (int qq = 0; qq < 4; qq++) {
                float dx = kx[qq] - jx, dy = ky[qq] - jy, dz = kz[qq] - jz;
                float d2 = dx * dx + dy * dy + dz * dz;
                if (kp[qq] && d2 < THR_F) conflict = true;
            }
            conflict = __any_sync(0xffffffffu, conflict);
            if (!conflict && lane == (j & 31)) kp[j >> 5] = true;
        }
        #pragma unroll
        for (int qq = 0; qq < 4; qq++) g_retain[b * Gg + lane + qq * 32] = kp[qq] ? 1 : 0;
    }
}

// ---------------------------------------------------------------------------
// Kernel 2: per-(group,batch) grid-culled ball query + top-32 + output
// ---------------------------------------------------------------------------
__global__ __launch_bounds__(GQ_T) void group_kernel(const float4* __restrict__ pts,
                                                     const int* __restrict__ lengths,
                                                     float* __restrict__ out) {
    const int g = blockIdx.x, b = blockIdx.y;
    const float* __restrict__ pf = (const float*)(pts + (size_t)b * Nn);
    const int t = threadIdx.x;
    const int len = lengths[b];

    const float cx = g_centers[((size_t)b * Gg + g) * 3 + 0];
    const float cy = g_centers[((size_t)b * Gg + g) * 3 + 1];
    const float cz = g_centers[((size_t)b * Gg + g) * 3 + 2];
    const int retain = g_retain[b * Gg + g];

    __shared__ int  s_segS[64];
    __shared__ int  s_segE[64];
    __shared__ u64t s_keys[256];
    __shared__ int  s_n;
    __shared__ int  s_tidx[GS];

    if (t == 0) s_n = 0;
    s_keys[t] = 0ull;
    s_keys[t + GQ_T] = 0ull;

    int lox = (int)floorf((cx - RADIUS_F) * 10.0f - 1e-4f); lox = lox < 0 ? 0 : lox;
    int hix = (int)floorf((cx + RADIUS_F) * 10.0f + 1e-4f); hix = hix > 9 ? 9 : hix;
    int loy = (int)floorf((cy - RADIUS_F) * 10.0f - 1e-4f); loy = loy < 0 ? 0 : loy;
    int hiy = (int)floorf((cy + RADIUS_F) * 10.0f + 1e-4f); hiy = hiy > 9 ? 9 : hiy;
    int loz = (int)floorf((cz - RADIUS_F) * 10.0f - 1e-4f); loz = loz < 0 ? 0 : loz;
    int hiz = (int)floorf((cz + RADIUS_F) * 10.0f + 1e-4f); hiz = hiz > 9 ? 9 : hiz;
    const int nx = hix - lox + 1, ny = hiy - loy + 1, nz = hiz - loz + 1;
    int nTot = retain ? (nx * ny * nz) : 0;

    int segCnt = 0;
    if (t < 64 && t < nTot) {
        const int ix = t % nx;
        const int iy = (t / nx) % ny;
        const int iz = t / (nx * ny);
        const int cell = ((loz + iz) * 10 + (loy + iy)) * 10 + (lox + ix);
        const int st = g_cellStart[b * (NCELL + 1) + cell];
        const int en = g_cellStart[b * (NCELL + 1) + cell + 1];
        s_segS[t] = st;
        segCnt = en - st;
    }
    if (t < 64) s_segE[t] = segCnt;
    __syncthreads();
    #pragma unroll
    for (int off = 1; off < 64; off <<= 1) {
        int x = (t >= off && t < 64) ? s_segE[t - off] : 0;
        __syncthreads();
        if (t < 64) s_segE[t] += x;
        __syncthreads();
    }
    const int C = (nTot > 0) ? s_segE[nTot - 1] : 0;
    if (t < 64) s_segE[t] -= segCnt;
    __syncthreads();

    const float4* __restrict__ bp = g_bpts + (size_t)b * Nn;
    const int* __restrict__ bi = g_bidx + (size_t)b * Nn;
    for (int pos = t; pos < C; pos += GQ_T) {
        int lo = 0, hi2 = nTot - 1;
        while (lo < hi2) {
            const int mid = (lo + hi2 + 1) >> 1;
            if (s_segE[mid] <= pos) lo = mid; else hi2 = mid - 1;
        }
        const int gp = s_segS[lo] + (pos - s_segE[lo]);
        float4 v = __ldg(bp + gp);
        const int idx = __ldg(bi + gp);
        const float dx = v.x - cx, dy = v.y - cy, dz = v.z - cz;
        const float d2 = dx * dx + dy * dy + dz * dz;
        if (d2 <= R2_F && idx < len) {
            const unsigned eb = __float_as_uint(v.w);
            const unsigned vb = (eb & 0x80000000u) ? ~eb : (eb | 0x80000000u);
            const int slot = atomicAdd(&s_n, 1);
            if (slot < 256)
                s_keys[slot] = ((u64t)vb << 32) | (u64t)(0xffffffffu - (unsigned)idx);
        }
    }
    __syncthreads();

    const int total = s_n;

    // cold path (never on this dataset): order by index, keep first UK
    if (total > UK) {
        #pragma unroll
        for (int k = 2; k <= 256; k <<= 1) {
            #pragma unroll
            for (int j = k >> 1; j > 0; j >>= 1) {
                #pragma unroll
                for (int e = 0; e < 2; e++) {
                    const int i = t + e * GQ_T;
                    const int l = i ^ j;
                    if (l > i) {
                        const u64t a = s_keys[i], c = s_keys[l];
                        const unsigned la = (unsigned)a, lc = (unsigned)c;
                        const bool up = ((i & k) == 0);
                        if (up ? (la < lc) : (la > lc)) { s_keys[i] = c; s_keys[l] = a; }
                    }
                }
                __syncthreads();
            }
        }
    }
    __syncthreads();

    const int numEff = total < UK ? total : UK;

    if (t < 32) {
        u64t key[4];
        #pragma unroll
        for (int rr = 0; rr < 4; rr++) {
            const int slot = rr * 32 + t;
            key[rr] = (slot < numEff) ? s_keys[slot] : 0ull;
        }
        #pragma unroll
        for (int k = 2; k <= 128; k <<= 1) {
            #pragma unroll
            for (int j = k >> 1; j > 0; j >>= 1) {
                if (j >= 32) {
                    const int rj = j >> 5;
                    #pragma unroll
                    for (int rr = 0; rr < 4; rr++) {
                        const int pr = rr ^ rj;
                        if (pr > rr) {
                            const int e = rr * 32 + t;
                            const bool dsc = ((e & k) == 0);
                            u64t a = key[rr], c = key[pr];
                            u64t mx = a > c ? a : c;
                            u64t mn = a > c ? c : a;
                            key[rr] = dsc ? mx : mn;
                            key[pr] = dsc ? mn : mx;
                        }
                    }
                } else {
                    #pragma unroll
                    for (int rr = 0; rr < 4; rr++) {
                        const int e = rr * 32 + t;
                        u64t o = __shfl_xor_sync(0xffffffffu, key[rr], j);
                        const bool low = ((t & j) == 0);
                        const bool dsc = ((e & k) == 0);
                        const bool takeMax = (dsc == low);
                        u64t mx = key[rr] > o ? key[rr] : o;
                        u64t mn = key[rr] > o ? o : key[rr];
                        key[rr] = takeMax ? mx : mn;
                    }
                }
            }
        }
        const u64t k0 = key[0];
        const int idx = (int)(0xffffffffu - (unsigned)k0);
        s_tidx[t] = ((unsigned)(k0 >> 32) >= 0x80000000u) ? idx : -1;
    }
    __syncthreads();

    {
        const int rr = t >> 2, c = t & 3;
        const int ti = s_tidx[rr];
        const int fi = (ti == -1) ? s_tidx[0] : ti;
        float val = (fi == -1) ? 0.0f : pf[(size_t)fi * 4 + c];
        if (c < 3) {
            const float cc = (c == 0) ? cx : (c == 1) ? cy : cz;
            val -= cc;
        }
        val = __fdiv_rn(val, RADIUS_F);
        out[OUT_GROUPS + ((((size_t)b * Gg + g) * GS) + rr) * Cc + c] = val;
    }
    if (t == 0 && total >= GS) atomicAdd(&g_glen[b], 1);
}

// ---------------------------------------------------------------------------
// Kernel 3: embedding mask
// ---------------------------------------------------------------------------
__global__ void mask_kernel(float* __restrict__ out) {
    const int i = blockIdx.x * blockDim.x + threadIdx.x;
    if (i < Bn * Gg) {
        const int b = i >> 7, g = i & (Gg - 1);
        out[OUT_MASK + i] = (g < g_glen[b]) ? 1.0f : 0.0f;
    }
}

extern "C" void kernel_launch(void* const* d_in, const int* in_sizes, int n_in,
                              void* d_out, int out_size) {
    const float4* pts = (const float4*)d_in[0];
    const int* lengths = (const int*)d_in[1];
    float* out = (float*)d_out;
    (void)in_sizes; (void)n_in; (void)out_size;

    fps_kernel<<<Bn * CLU + Bn, FT>>>(pts, lengths, out);
    group_kernel<<<dim3(Gg, Bn), GQ_T>>>(pts, lengths, out);
    mask_kernel<<<(Bn * Gg + 255) / 256, 256>>>(out);
}

// round 12
// speedup vs baseline: 1.9598x; 1.0186x over previous
#include <cuda_runtime.h>
#include <cuda_bf16.h>
#include <cstdint>

// Problem constants
#define Bn 8
#define Nn 16384
#define Cc 4
#define Gg 128          // NUM_GROUPS
#define GS 32           // GROUP_SIZE
#define UK 128          // UPSCALE_K
#define CLU 4           // cluster size for FPS
#define FT 1024         // threads per CTA (fps + bin)
#define PPC (Nn / CLU)  // 4096 points per FPS CTA
#define FPAIR 2         // packed pairs per thread
#define GQ_T 128        // group kernel threads
#define NCELL 1000      // 10x10x10 grid

typedef unsigned long long u64t;

__device__ __forceinline__ float NEG_INF() { return __int_as_float(0xff800000); }
__device__ __forceinline__ float POS_INF() { return __int_as_float(0x7f800000); }
#define RADIUS_F 0.1f
#define R2_F 0.01f                  // f32(0.01)
#define THR_F 0.0036f               // f32((2*0.1*0.3)^2)

// Output layout: groups | centers | mask
#define OUT_GROUPS 0
#define OUT_CENTERS (Bn * Gg * GS * Cc)          // 131072
#define OUT_MASK (OUT_CENTERS + Bn * Gg * 3)     // 134144

__device__ float  g_centers[Bn * Gg * 3];
__device__ int    g_retain[Bn * Gg];
__device__ int    g_glen[Bn];
__device__ int    g_cellStart[Bn * (NCELL + 1)];
__device__ float4 g_bpts[Bn * Nn];
__device__ int    g_bidx[Bn * Nn];

// ---- f32x2 packed helpers (sm_100+) ----
__device__ __forceinline__ u64t pk2(float lo, float hi) {
    u64t r; asm("mov.b64 %0, {%1, %2};" : "=l"(r) : "f"(lo), "f"(hi)); return r;
}
__device__ __forceinline__ float plo(u64t v) { return __uint_as_float((unsigned)v); }
__device__ __forceinline__ float phi(u64t v) { return __uint_as_float((unsigned)(v >> 32)); }
__device__ __forceinline__ u64t add2(u64t a, u64t b) {
    u64t r; asm("add.rn.f32x2 %0, %1, %2;" : "=l"(r) : "l"(a), "l"(b)); return r;
}
__device__ __forceinline__ u64t mul2(u64t a, u64t b) {
    u64t r; asm("mul.rn.f32x2 %0, %1, %2;" : "=l"(r) : "l"(a), "l"(b)); return r;
}
__device__ __forceinline__ u64t fma2(u64t a, u64t b, u64t c) {
    u64t r; asm("fma.rn.f32x2 %0, %1, %2, %3;" : "=l"(r) : "l"(a), "l"(b), "l"(c)); return r;
}

// ---- cluster helpers ----
__device__ __forceinline__ uint32_t smem_u32(const void* p) {
    uint32_t a;
    asm("{ .reg .u64 t; cvta.to.shared.u64 t, %1; cvt.u32.u64 %0, t; }" : "=r"(a) : "l"(p));
    return a;
}
__device__ __forceinline__ void st_clu_u64(uint32_t laddr, uint32_t rank, u64t v) {
    uint32_t ra;
    asm("mapa.shared::cluster.u32 %0, %1, %2;" : "=r"(ra) : "r"(laddr), "r"(rank));
    asm volatile("st.shared::cluster.u64 [%0], %1;" :: "r"(ra), "l"(v) : "memory");
}
__device__ __forceinline__ void st_clu_f32(uint32_t laddr, uint32_t rank, float v) {
    uint32_t ra;
    asm("mapa.shared::cluster.u32 %0, %1, %2;" : "=r"(ra) : "r"(laddr), "r"(rank));
    asm volatile("st.shared::cluster.f32 [%0], %1;" :: "r"(ra), "f"(v) : "memory");
}
__device__ __forceinline__ void mbar_init(uint32_t addr, uint32_t count) {
    asm volatile("mbarrier.init.shared.b64 [%0], %1;" :: "r"(addr), "r"(count) : "memory");
}
__device__ __forceinline__ void mbar_arrive_rel_cluster(uint32_t laddr, uint32_t rank) {
    uint32_t ra;
    asm("mapa.shared::cluster.u32 %0, %1, %2;" : "=r"(ra) : "r"(laddr), "r"(rank));
    asm volatile("mbarrier.arrive.release.cluster.shared::cluster.b64 _, [%0];"
                 :: "r"(ra) : "memory");
}
__device__ __forceinline__ void mbar_wait_acq_cluster(uint32_t addr, uint32_t parity) {
    asm volatile(
        "{\n\t.reg .pred P;\n\t"
        "WL_%=:\n\t"
        "mbarrier.try_wait.parity.acquire.cluster.shared::cta.b64 P, [%0], %1, 0x989680;\n\t"
        "@P bra.uni WD_%=;\n\t"
        "bra.uni WL_%=;\n\t"
        "WD_%=:\n\t}"
        :: "r"(addr), "r"(parity) : "memory");
}
__device__ __forceinline__ void cluster_sync_() {
    asm volatile("barrier.cluster.arrive.aligned;" ::: "memory");
    asm volatile("barrier.cluster.wait.aligned;" ::: "memory");
}

__device__ __forceinline__ int cell_of(float x, float y, float z) {
    int cx = (int)(x * 10.0f); cx = cx < 0 ? 0 : (cx > 9 ? 9 : cx);
    int cy = (int)(y * 10.0f); cy = cy < 0 ? 0 : (cy > 9 ? 9 : cy);
    int cz = (int)(z * 10.0f); cz = cz < 0 ? 0 : (cz > 9 ? 9 : cz);
    return (cz * 10 + cy) * 10 + cx;
}

// ---------------------------------------------------------------------------
// Kernel 1: blocks [0, Bn*CLU): cluster-parallel FPS
//           blocks [Bn*CLU, Bn*CLU+Bn): per-batch grid binning (overlapped)
// ---------------------------------------------------------------------------
__global__ __launch_bounds__(FT) __cluster_dims__(CLU, 1, 1)
void fps_kernel(const float4* __restrict__ pts,
                const int* __restrict__ lengths,
                float* __restrict__ out) {
    const int bid = blockIdx.x;
    const int t = threadIdx.x;

    if (bid >= Bn * CLU) {
        // ---------------- binning path ----------------
        const int b = bid - Bn * CLU;
        const float4* __restrict__ p = pts + (size_t)b * Nn;
        __shared__ int s_cnt[NCELL];
        __shared__ int s_scan[FT];

        if (t < NCELL) s_cnt[t] = 0;
        __syncthreads();

        int cellr[16];
        #pragma unroll
        for (int k = 0; k < 16; k++) {
            const int i = t + k * FT;
            float4 v = __ldg(p + i);
            const int c = cell_of(v.x, v.y, v.z);
            cellr[k] = c;
            atomicAdd(&s_cnt[c], 1);
        }
        __syncthreads();

        const int myc = (t < NCELL) ? s_cnt[t] : 0;
        s_scan[t] = myc;
        __syncthreads();
        #pragma unroll
        for (int off = 1; off < FT; off <<= 1) {
            int x = (t >= off) ? s_scan[t - off] : 0;
            __syncthreads();
            s_scan[t] += x;
            __syncthreads();
        }
        const int excl = s_scan[t] - myc;
        if (t < NCELL) g_cellStart[b * (NCELL + 1) + t] = excl;
        if (t == 0) g_cellStart[b * (NCELL + 1) + NCELL] = Nn;
        __syncthreads();
        if (t < NCELL) s_cnt[t] = excl;      // running cursors
        __syncthreads();

        #pragma unroll
        for (int k = 0; k < 16; k++) {
            const int i = t + k * FT;
            const int pos = atomicAdd(&s_cnt[cellr[k]], 1);
            g_bpts[(size_t)b * Nn + pos] = __ldg(p + i);
            g_bidx[(size_t)b * Nn + pos] = i;
        }
        return;
    }

    // ---------------- FPS path ----------------
    const int b = bid / CLU;
    const int r = bid % CLU;
    const float4* __restrict__ p = pts + (size_t)b * Nn;
    const int len = lengths[b];
    const int lane = t & 31, warp = t >> 5;
    const int base = r * PPC;

    __shared__ u64t  s_wk[32];
    __shared__ u64t  s_wxy[32];
    __shared__ float s_wz[32];
    __shared__ __align__(16) ulonglong2 s_pack[2][CLU];   // {key, xy} per rank
    __shared__ float s_sz[2][CLU];
    __shared__ float s_c[3];
    __shared__ __align__(8) unsigned char s_bar[2][8];
    __shared__ float s_centers[Gg * 3];

    const uint32_t a_pack = smem_u32(&s_pack[0][0]);
    const uint32_t a_sz   = smem_u32(&s_sz[0][0]);
    const uint32_t a_bar  = smem_u32(&s_bar[0][0]);

    if (t == 0) {
        mbar_init(a_bar, CLU);
        mbar_init(a_bar + 8, CLU);
        if (r == 0) g_glen[b] = 0;
    }

    u64t Xp[FPAIR], Yp[FPAIR], Zp[FPAIR];
    float Mlo[FPAIR], Mhi[FPAIR];
    #pragma unroll
    for (int j = 0; j < FPAIR; j++) {
        const int i0 = base + t + (2 * j) * FT;
        const int i1 = i0 + FT;
        float4 a = __ldg(p + i0);
        float4 c = __ldg(p + i1);
        Xp[j] = pk2(a.x, c.x);
        Yp[j] = pk2(a.y, c.y);
        Zp[j] = pk2(a.z, c.z);
        Mlo[j] = (i0 < len) ? POS_INF() : NEG_INF();
        Mhi[j] = (i1 < len) ? POS_INF() : NEG_INF();
    }

    float4 c0 = __ldg(p);
    float cx = c0.x, cy = c0.y, cz = c0.z;
    if (r == 0 && t == 0) {
        s_centers[0] = cx; s_centers[1] = cy; s_centers[2] = cz;
    }

    // barriers must be cluster-visible before any remote arrive
    __syncthreads();
    cluster_sync_();

    unsigned ph0 = 0, ph1 = 0;

    for (int s = 1; s < Gg; s++) {
        const int q = s & 1;
        const u64t ncx = pk2(-cx, -cx);
        const u64t ncy = pk2(-cy, -cy);
        const u64t ncz = pk2(-cz, -cz);

        #pragma unroll
        for (int j = 0; j < FPAIR; j++) {
            u64t dx = add2(Xp[j], ncx);
            u64t dy = add2(Yp[j], ncy);
            u64t dz = add2(Zp[j], ncz);
            u64t d = mul2(dx, dx);
            d = fma2(dy, dy, d);
            d = fma2(dz, dz, d);
            Mlo[j] = fminf(Mlo[j], plo(d));
            Mhi[j] = fminf(Mhi[j], phi(d));
        }

        float bv = fmaxf(fmaxf(Mlo[0], Mhi[0]), fmaxf(Mlo[1], Mhi[1]));
        const int bb = __float_as_int(bv);
        const int wmax = __reduce_max_sync(0xffffffffu, bb);

        int bk = 3;
        if (Mlo[1] == bv) bk = 2;
        if (Mhi[0] == bv) bk = 1;
        if (Mlo[0] == bv) bk = 0;

        unsigned gl = (bb == wmax) ? ((unsigned)(bk << 10) + (unsigned)t) : 0xffffffffu;
        const unsigned gmin = __reduce_min_sync(0xffffffffu, gl);

        const unsigned tv = (wmax >= 0) ? ((unsigned)wmax | 0x80000000u) : ~(unsigned)wmax;
        const u64t wkey = ((u64t)tv << 32) | (u64t)(0xffffffffu - (unsigned)(base + (int)gmin));

        // winner lane writes its own key + coords (no shuffles)
        if (gl == gmin) {
            const int jj = bk >> 1;
            const bool hi = bk & 1;
            const float sx = hi ? phi(Xp[jj]) : plo(Xp[jj]);
            const float sy = hi ? phi(Yp[jj]) : plo(Yp[jj]);
            const float sz = hi ? phi(Zp[jj]) : plo(Zp[jj]);
            s_wk[warp] = wkey;
            s_wxy[warp] = pk2(sx, sy);
            s_wz[warp] = sz;
        }
        __syncthreads();

        // warps 0..3 each combine the 32 warp winners and push to rank=warp
        if (warp < CLU) {
            const u64t k = s_wk[lane];
            const unsigned tvp = (unsigned)(k >> 32);
            const unsigned lowp = (unsigned)k;
            const unsigned tmax = __reduce_max_sync(0xffffffffu, tvp);
            const unsigned lw = (tvp == tmax) ? lowp : 0u;
            const unsigned lmax = __reduce_max_sync(0xffffffffu, lw); // max(~gidx) = min gidx
            const u64t m = ((u64t)tmax << 32) | (u64t)lmax;
            const unsigned ball = __ballot_sync(0xffffffffu, (tvp == tmax) && (lowp == lmax));
            const int srcw = __ffs(ball) - 1;
            if (lane == 0) {
                const u64t xy = s_wxy[srcw];
                const float z = s_wz[srcw];
                const uint32_t off16 = (uint32_t)(q * CLU + r) * 16;
                const uint32_t off4  = (uint32_t)(q * CLU + r) * 4;
                st_clu_u64(a_pack + off16, (uint32_t)warp, m);
                st_clu_u64(a_pack + off16 + 8, (uint32_t)warp, xy);
                st_clu_f32(a_sz + off4, (uint32_t)warp, z);
                mbar_arrive_rel_cluster(a_bar + (uint32_t)q * 8, (uint32_t)warp);
            }
        }

        // warp0 alone waits for the 4 rank pushes, picks winner, broadcasts
        if (warp == 0) {
            if (q) { mbar_wait_acq_cluster(a_bar + 8, ph1); ph1 ^= 1u; }
            else   { mbar_wait_acq_cluster(a_bar, ph0); ph0 ^= 1u; }

            if (lane == 0) {
                const ulonglong2* pk = &s_pack[q][0];
                u64t km = pk[0].x;
                int w = 0;
                #pragma unroll
                for (int i = 1; i < CLU; i++) {
                    const u64t ki = pk[i].x;
                    if (ki > km) { km = ki; w = i; }
                }
                const u64t wxy = pk[w].y;
                const float wx = plo(wxy), wy = phi(wxy), wz = s_sz[q][w];
                s_c[0] = wx; s_c[1] = wy; s_c[2] = wz;
                if (r == 0) {
                    s_centers[s * 3 + 0] = wx;
                    s_centers[s * 3 + 1] = wy;
                    s_centers[s * 3 + 2] = wz;
                }
            }
        }
        __syncthreads();
        cx = s_c[0]; cy = s_c[1]; cz = s_c[2];
    }

    cluster_sync_();
    if (r != 0) return;

    for (int i = t; i < Gg * 3; i += FT) {
        float v = s_centers[i];
        g_centers[(size_t)b * Gg * 3 + i] = v;
        out[OUT_CENTERS + (size_t)b * Gg * 3 + i] = v;
    }

    if (t < 32) {
        float kx[4], ky[4], kz[4];
        bool kp[4];
        #pragma unroll
        for (int qq = 0; qq < 4; qq++) {
            const int i = lane + qq * 32;
            kx[qq] = s_centers[i * 3 + 0];
            ky[qq] = s_centers[i * 3 + 1];
            kz[qq] = s_centers[i * 3 + 2];
            kp[qq] = false;
        }
        for (int j = 0; j < Gg; j++) {
            const float jx = s_centers[j * 3 + 0];
            const float jy = s_centers[j * 3 + 1];
            const float jz = s_centers[j * 3 + 2];
            bool conflict = false;
            #pragma unroll
            for (int qq = 0; qq < 4; qq++) {
                float dx = kx[qq] - jx, dy = ky[qq] - jy, dz = kz[qq] - jz;
                float d2 = dx * dx + dy * dy + dz * dz;
                if (kp[qq] && d2 < THR_F) conflict = true;
            }
            conflict = __any_sync(0xffffffffu, conflict);
            if (!conflict && lane == (j & 31)) kp[j >> 5] = true;
        }
        #pragma unroll
        for (int qq = 0; qq < 4; qq++) g_retain[b * Gg + lane + qq * 32] = kp[qq] ? 1 : 0;
    }
}

// ---------------------------------------------------------------------------
// Kernel 2: per-(group,batch) grid-culled ball query + top-32 + output
// ---------------------------------------------------------------------------
__global__ __launch_bounds__(GQ_T) void group_kernel(const float4* __restrict__ pts,
                                                     const int* __restrict__ lengths,
                                                     float* __restrict__ out) {
    const int g = blockIdx.x, b = blockIdx.y;
    const float* __restrict__ pf = (const float*)(pts + (size_t)b * Nn);
    const int t = threadIdx.x;
    const int len = lengths[b];

    const float cx = g_centers[((size_t)b * Gg + g) * 3 + 0];
    const float cy = g_centers[((size_t)b * Gg + g) * 3 + 1];
    const float cz = g_centers[((size_t)b * Gg + g) * 3 + 2];
    const int retain = g_retain[b * Gg + g];

    __shared__ int  s_segS[64];
    __shared__ int  s_segE[64];
    __shared__ u64t s_keys[256];
    __shared__ int  s_n;
    __shared__ int  s_tidx[GS];

    if (t == 0) s_n = 0;
    s_keys[t] = 0ull;
    s_keys[t + GQ_T] = 0ull;

    int lox = (int)floorf((cx - RADIUS_F) * 10.0f - 1e-4f); lox = lox < 0 ? 0 : lox;
    int hix = (int)floorf((cx + RADIUS_F) * 10.0f + 1e-4f); hix = hix > 9 ? 9 : hix;
    int loy = (int)floorf((cy - RADIUS_F) * 10.0f - 1e-4f); loy = loy < 0 ? 0 : loy;
    int hiy = (int)floorf((cy + RADIUS_F) * 10.0f + 1e-4f); hiy = hiy > 9 ? 9 : hiy;
    int loz = (int)floorf((cz - RADIUS_F) * 10.0f - 1e-4f); loz = loz < 0 ? 0 : loz;
    int hiz = (int)floorf((cz + RADIUS_F) * 10.0f + 1e-4f); hiz = hiz > 9 ? 9 : hiz;
    const int nx = hix - lox + 1, ny = hiy - loy + 1, nz = hiz - loz + 1;
    int nTot = retain ? (nx * ny * nz) : 0;

    int segCnt = 0;
    if (t < 64 && t < nTot) {
        const int ix = t % nx;
        const int iy = (t / nx) % ny;
        const int iz = t / (nx * ny);
        const int cell = ((loz + iz) * 10 + (loy + iy)) * 10 + (lox + ix);
        const int st = g_cellStart[b * (NCELL + 1) + cell];
        const int en = g_cellStart[b * (NCELL + 1) + cell + 1];
        s_segS[t] = st;
        segCnt = en - st;
    }
    if (t < 64) s_segE[t] = segCnt;
    __syncthreads();
    #pragma unroll
    for (int off = 1; off < 64; off <<= 1) {
        int x = (t >= off && t < 64) ? s_segE[t - off] : 0;
        __syncthreads();
        if (t < 64) s_segE[t] += x;
        __syncthreads();
    }
    const int C = (nTot > 0) ? s_segE[nTot - 1] : 0;
    if (t < 64) s_segE[t] -= segCnt;
    __syncthreads();

    const float4* __restrict__ bp = g_bpts + (size_t)b * Nn;
    const int* __restrict__ bi = g_bidx + (size_t)b * Nn;
    for (int pos = t; pos < C; pos += GQ_T) {
        int lo = 0, hi2 = nTot - 1;
        while (lo < hi2) {
            const int mid = (lo + hi2 + 1) >> 1;
            if (s_segE[mid] <= pos) lo = mid; else hi2 = mid - 1;
        }
        const int gp = s_segS[lo] + (pos - s_segE[lo]);
        float4 v = __ldg(bp + gp);
        const int idx = __ldg(bi + gp);
        const float dx = v.x - cx, dy = v.y - cy, dz = v.z - cz;
        const float d2 = dx * dx + dy * dy + dz * dz;
        if (d2 <= R2_F && idx < len) {
            const unsigned eb = __float_as_uint(v.w);
            const unsigned vb = (eb & 0x80000000u) ? ~eb : (eb | 0x80000000u);
            const int slot = atomicAdd(&s_n, 1);
            if (slot < 256)
                s_keys[slot] = ((u64t)vb << 32) | (u64t)(0xffffffffu - (unsigned)idx);
        }
    }
    __syncthreads();

    const int total = s_n;

    // cold path (never on this dataset): order by index, keep first UK
    if (total > UK) {
        #pragma unroll
        for (int k = 2; k <= 256; k <<= 1) {
            #pragma unroll
            for (int j = k >> 1; j > 0; j >>= 1) {
                #pragma unroll
                for (int e = 0; e < 2; e++) {
                    const int i = t + e * GQ_T;
                    const int l = i ^ j;
                    if (l > i) {
                        const u64t a = s_keys[i], c = s_keys[l];
                        const unsigned la = (unsigned)a, lc = (unsigned)c;
                        const bool up = ((i & k) == 0);
                        if (up ? (la < lc) : (la > lc)) { s_keys[i] = c; s_keys[l] = a; }
                    }
                }
                __syncthreads();
            }
        }
    }
    __syncthreads();

    const int numEff = total < UK ? total : UK;

    if (t < 32) {
        u64t key[4];
        #pragma unroll
        for (int rr = 0; rr < 4; rr++) {
            const int slot = rr * 32 + t;
            key[rr] = (slot < numEff) ? s_keys[slot] : 0ull;
        }
        #pragma unroll
        for (int k = 2; k <= 128; k <<= 1) {
            #pragma unroll
            for (int j = k >> 1; j > 0; j >>= 1) {
                if (j >= 32) {
                    const int rj = j >> 5;
                    #pragma unroll
                    for (int rr = 0; rr < 4; rr++) {
                        const int pr = rr ^ rj;
                        if (pr > rr) {
                            const int e = rr * 32 + t;
                            const bool dsc = ((e & k) == 0);
                            u64t a = key[rr], c = key[pr];
                            u64t mx = a > c ? a : c;
                            u64t mn = a > c ? c : a;
                            key[rr] = dsc ? mx : mn;
                            key[pr] = dsc ? mn : mx;
                        }
                    }
                } else {
                    #pragma unroll
                    for (int rr = 0; rr < 4; rr++) {
                        const int e = rr * 32 + t;
                        u64t o = __shfl_xor_sync(0xffffffffu, key[rr], j);
                        const bool low = ((t & j) == 0);
                        const bool dsc = ((e & k) == 0);
                        const bool takeMax = (dsc == low);
                        u64t mx = key[rr] > o ? key[rr] : o;
                        u64t mn = key[rr] > o ? o : key[rr];
                        key[rr] = takeMax ? mx : mn;
                    }
                }
            }
        }
        const u64t k0 = key[0];
        const int idx = (int)(0xffffffffu - (unsigned)k0);
        s_tidx[t] = ((unsigned)(k0 >> 32) >= 0x80000000u) ? idx : -1;
    }
    __syncthreads();

    {
        const int rr = t >> 2, c = t & 3;
        const int ti = s_tidx[rr];
        const int fi = (ti == -1) ? s_tidx[0] : ti;
        float val = (fi == -1) ? 0.0f : pf[(size_t)fi * 4 + c];
        if (c < 3) {
            const float cc = (c == 0) ? cx : (c == 1) ? cy : cz;
            val -= cc;
        }
        val = __fdiv_rn(val, RADIUS_F);
        out[OUT_GROUPS + ((((size_t)b * Gg + g) * GS) + rr) * Cc + c] = val;
    }
    if (t == 0 && total >= GS) atomicAdd(&g_glen[b], 1);
}

// ---------------------------------------------------------------------------
// Kernel 3: embedding mask
// ---------------------------------------------------------------------------
__global__ void mask_kernel(float* __restrict__ out) {
    const int i = blockIdx.x * blockDim.x + threadIdx.x;
    if (i < Bn * Gg) {
        const int b = i >> 7, g = i & (Gg - 1);
        out[OUT_MASK + i] = (g < g_glen[b]) ? 1.0f : 0.0f;
    }
}

extern "C" void kernel_launch(void* const* d_in, const int* in_sizes, int n_in,
                              void* d_out, int out_size) {
    const float4* pts = (const float4*)d_in[0];
    const int* lengths = (const int*)d_in[1];
    float* out = (float*)d_out;
    (void)in_sizes; (void)n_in; (void)out_size;

    fps_kernel<<<Bn * CLU + Bn, FT>>>(pts, lengths, out);
    group_kernel<<<dim3(Gg, Bn), GQ_T>>>(pts, lengths, out);
    mask_kernel<<<(Bn * Gg + 255) / 256, 256>>>(out);
}

// round 14
// speedup vs baseline: 2.4093x; 1.2293x over previous
#include <cuda_runtime.h>
#include <cuda_bf16.h>
#include <cstdint>

// Problem constants
#define Bn 8
#define Nn 16384
#define Cc 4
#define Gg 128          // NUM_GROUPS
#define GS 32           // GROUP_SIZE
#define UK 128          // UPSCALE_K
#define CLU 4           // cluster size for FPS
#define FT 256          // threads per CTA (fps + bin)
#define NW (FT / 32)    // 8 warps
#define PPC (Nn / CLU)  // 4096 points per FPS CTA
#define FPAIR (PPC / FT / 2)   // 8 packed pairs (16 pts) per thread
#define GQ_T 128        // group kernel threads
#define NCELL 1000      // 10x10x10 grid

typedef unsigned long long u64t;

__device__ __forceinline__ float NEG_INF() { return __int_as_float(0xff800000); }
__device__ __forceinline__ float POS_INF() { return __int_as_float(0x7f800000); }
#define RADIUS_F 0.1f
#define R2_F 0.01f                  // f32(0.01)
#define THR_F 0.0036f               // f32((2*0.1*0.3)^2)

// Output layout: groups | centers | mask
#define OUT_GROUPS 0
#define OUT_CENTERS (Bn * Gg * GS * Cc)          // 131072
#define OUT_MASK (OUT_CENTERS + Bn * Gg * 3)     // 134144

__device__ float  g_centers[Bn * Gg * 3];
__device__ int    g_retain[Bn * Gg];
__device__ int    g_glen[Bn];
__device__ int    g_cellStart[Bn * (NCELL + 1)];
__device__ float4 g_bpts[Bn * Nn];
__device__ int    g_bidx[Bn * Nn];

// ---- f32x2 packed helpers (sm_100+) ----
__device__ __forceinline__ u64t pk2(float lo, float hi) {
    u64t r; asm("mov.b64 %0, {%1, %2};" : "=l"(r) : "f"(lo), "f"(hi)); return r;
}
__device__ __forceinline__ float plo(u64t v) { return __uint_as_float((unsigned)v); }
__device__ __forceinline__ float phi(u64t v) { return __uint_as_float((unsigned)(v >> 32)); }
__device__ __forceinline__ u64t add2(u64t a, u64t b) {
    u64t r; asm("add.rn.f32x2 %0, %1, %2;" : "=l"(r) : "l"(a), "l"(b)); return r;
}
__device__ __forceinline__ u64t mul2(u64t a, u64t b) {
    u64t r; asm("mul.rn.f32x2 %0, %1, %2;" : "=l"(r) : "l"(a), "l"(b)); return r;
}
__device__ __forceinline__ u64t fma2(u64t a, u64t b, u64t c) {
    u64t r; asm("fma.rn.f32x2 %0, %1, %2, %3;" : "=l"(r) : "l"(a), "l"(b), "l"(c)); return r;
}

// ---- cluster helpers ----
__device__ __forceinline__ uint32_t smem_u32(const void* p) {
    uint32_t a;
    asm("{ .reg .u64 t; cvta.to.shared.u64 t, %1; cvt.u32.u64 %0, t; }" : "=r"(a) : "l"(p));
    return a;
}
__device__ __forceinline__ void st_clu_u64(uint32_t laddr, uint32_t rank, u64t v) {
    uint32_t ra;
    asm("mapa.shared::cluster.u32 %0, %1, %2;" : "=r"(ra) : "r"(laddr), "r"(rank));
    asm volatile("st.shared::cluster.u64 [%0], %1;" :: "r"(ra), "l"(v) : "memory");
}
__device__ __forceinline__ void st_clu_f32(uint32_t laddr, uint32_t rank, float v) {
    uint32_t ra;
    asm("mapa.shared::cluster.u32 %0, %1, %2;" : "=r"(ra) : "r"(laddr), "r"(rank));
    asm volatile("st.shared::cluster.f32 [%0], %1;" :: "r"(ra), "f"(v) : "memory");
}
__device__ __forceinline__ void mbar_init(uint32_t addr, uint32_t count) {
    asm volatile("mbarrier.init.shared.b64 [%0], %1;" :: "r"(addr), "r"(count) : "memory");
}
__device__ __forceinline__ void mbar_arrive_rel_cluster(uint32_t laddr, uint32_t rank) {
    uint32_t ra;
    asm("mapa.shared::cluster.u32 %0, %1, %2;" : "=r"(ra) : "r"(laddr), "r"(rank));
    asm volatile("mbarrier.arrive.release.cluster.shared::cluster.b64 _, [%0];"
                 :: "r"(ra) : "memory");
}
__device__ __forceinline__ void mbar_wait_acq_cluster(uint32_t addr, uint32_t parity) {
    asm volatile(
        "{\n\t.reg .pred P;\n\t"
        "WL_%=:\n\t"
        "mbarrier.try_wait.parity.acquire.cluster.shared::cta.b64 P, [%0], %1, 0x989680;\n\t"
        "@P bra.uni WD_%=;\n\t"
        "bra.uni WL_%=;\n\t"
        "WD_%=:\n\t}"
        :: "r"(addr), "r"(parity) : "memory");
}
__device__ __forceinline__ void cluster_sync_() {
    asm volatile("barrier.cluster.arrive.aligned;" ::: "memory");
    asm volatile("barrier.cluster.wait.aligned;" ::: "memory");
}

__device__ __forceinline__ int cell_of(float x, float y, float z) {
    int cx = (int)(x * 10.0f); cx = cx < 0 ? 0 : (cx > 9 ? 9 : cx);
    int cy = (int)(y * 10.0f); cy = cy < 0 ? 0 : (cy > 9 ? 9 : cy);
    int cz = (int)(z * 10.0f); cz = cz < 0 ? 0 : (cz > 9 ? 9 : cz);
    return (cz * 10 + cy) * 10 + cx;
}

// ---------------------------------------------------------------------------
// Kernel 1: blocks [0, Bn*CLU): cluster-parallel FPS (256 threads, 8 warps)
//           blocks [Bn*CLU, Bn*CLU+Bn): per-batch grid binning (overlapped)
// ---------------------------------------------------------------------------
__global__ __launch_bounds__(FT) __cluster_dims__(CLU, 1, 1)
void fps_kernel(const float4* __restrict__ pts,
                const int* __restrict__ lengths,
                float* __restrict__ out) {
    const int bid = blockIdx.x;
    const int t = threadIdx.x;
    const int lane = t & 31, warp = t >> 5;

    if (bid >= Bn * CLU) {
        // ---------------- binning path (256 threads) ----------------
        const int b = bid - Bn * CLU;
        const float4* __restrict__ p = pts + (size_t)b * Nn;
        __shared__ int s_cnt[NCELL];
        __shared__ int s_ws[NW];

        for (int i = t; i < NCELL; i += FT) s_cnt[i] = 0;
        __syncthreads();

        // count (recompute cells later instead of caching)
        for (int k = 0; k < Nn / FT; k++) {
            const int i = t + k * FT;
            float4 v = __ldg(p + i);
            atomicAdd(&s_cnt[cell_of(v.x, v.y, v.z)], 1);
        }
        __syncthreads();

        // scan: thread t owns cells [4t, 4t+4)
        int c4[4];
        int T = 0;
        #pragma unroll
        for (int j = 0; j < 4; j++) {
            const int i = 4 * t + j;
            c4[j] = (i < NCELL) ? s_cnt[i] : 0;
            T += c4[j];
        }
        int v = T;
        #pragma unroll
        for (int off = 1; off < 32; off <<= 1) {
            int o = __shfl_up_sync(0xffffffffu, v, off);
            if (lane >= off) v += o;
        }
        if (lane == 31) s_ws[warp] = v;
        __syncthreads();
        if (t < NW) {
            int w = s_ws[t];
            #pragma unroll
            for (int off = 1; off < NW; off <<= 1) {
                int o = __shfl_up_sync((1u << NW) - 1u, w, off);
                if (t >= off) w += o;
            }
            s_ws[t] = w;
        }
        __syncthreads();
        int run = ((warp == 0) ? 0 : s_ws[warp - 1]) + v - T;
        int ex4[4];
        #pragma unroll
        for (int j = 0; j < 4; j++) { ex4[j] = run; run += c4[j]; }
        __syncthreads();     // all s_cnt reads done; safe to overwrite
        #pragma unroll
        for (int j = 0; j < 4; j++) {
            const int i = 4 * t + j;
            if (i < NCELL) {
                g_cellStart[b * (NCELL + 1) + i] = ex4[j];
                s_cnt[i] = ex4[j];           // running cursor
            }
        }
        if (t == 0) g_cellStart[b * (NCELL + 1) + NCELL] = Nn;
        __syncthreads();

        // scatter
        for (int k = 0; k < Nn / FT; k++) {
            const int i = t + k * FT;
            float4 vv = __ldg(p + i);
            const int c = cell_of(vv.x, vv.y, vv.z);
            const int pos = atomicAdd(&s_cnt[c], 1);
            g_bpts[(size_t)b * Nn + pos] = vv;
            g_bidx[(size_t)b * Nn + pos] = i;
        }
        return;
    }

    // ---------------- FPS path ----------------
    const int b = bid / CLU;
    const int r = bid % CLU;
    const float4* __restrict__ p = pts + (size_t)b * Nn;
    const int len = lengths[b];
    const int base = r * PPC;

    __shared__ u64t  s_wk[NW];
    __shared__ u64t  s_wxy[NW];
    __shared__ float s_wz[NW];
    __shared__ __align__(16) ulonglong2 s_pack[2][CLU];   // {key, xy} per rank
    __shared__ float s_sz[2][CLU];
    __shared__ float s_c[3];
    __shared__ __align__(8) unsigned char s_bar[2][8];
    __shared__ float s_centers[Gg * 3];

    const uint32_t a_pack = smem_u32(&s_pack[0][0]);
    const uint32_t a_sz   = smem_u32(&s_sz[0][0]);
    const uint32_t a_bar  = smem_u32(&s_bar[0][0]);

    if (t == 0) {
        mbar_init(a_bar, CLU);
        mbar_init(a_bar + 8, CLU);
        if (r == 0) g_glen[b] = 0;
    }

    // 16 pts/thread as 8 pairs: pair j = local idx (t + 2j*256, t + (2j+1)*256)
    u64t Xp[FPAIR], Yp[FPAIR], Zp[FPAIR];
    float Mlo[FPAIR], Mhi[FPAIR];
    #pragma unroll
    for (int j = 0; j < FPAIR; j++) {
        const int i0 = base + t + (2 * j) * FT;
        const int i1 = i0 + FT;
        float4 a = __ldg(p + i0);
        float4 c = __ldg(p + i1);
        Xp[j] = pk2(a.x, c.x);
        Yp[j] = pk2(a.y, c.y);
        Zp[j] = pk2(a.z, c.z);
        Mlo[j] = (i0 < len) ? POS_INF() : NEG_INF();
        Mhi[j] = (i1 < len) ? POS_INF() : NEG_INF();
    }

    float4 c0 = __ldg(p);
    float cx = c0.x, cy = c0.y, cz = c0.z;
    if (r == 0 && t == 0) {
        s_centers[0] = cx; s_centers[1] = cy; s_centers[2] = cz;
    }

    // barriers must be cluster-visible before any remote arrive
    __syncthreads();
    cluster_sync_();

    unsigned ph0 = 0, ph1 = 0;

    for (int s = 1; s < Gg; s++) {
        const int q = s & 1;
        const u64t ncx = pk2(-cx, -cx);
        const u64t ncy = pk2(-cy, -cy);
        const u64t ncz = pk2(-cz, -cz);

        #pragma unroll
        for (int j = 0; j < FPAIR; j++) {
            u64t dx = add2(Xp[j], ncx);
            u64t dy = add2(Yp[j], ncy);
            u64t dz = add2(Zp[j], ncz);
            u64t d = mul2(dx, dx);
            d = fma2(dy, dy, d);
            d = fma2(dz, dz, d);
            Mlo[j] = fminf(Mlo[j], plo(d));
            Mhi[j] = fminf(Mhi[j], phi(d));
        }

        // thread-local max over 16 mins
        float bv = NEG_INF();
        #pragma unroll
        for (int j = 0; j < FPAIR; j++) bv = fmaxf(bv, fmaxf(Mlo[j], Mhi[j]));

        const int bb = __float_as_int(bv);
        const int wmax = __reduce_max_sync(0xffffffffu, bb);

        // min local slot k (0..15) matching bv
        int bk = 2 * FPAIR - 1;
        #pragma unroll
        for (int j = FPAIR - 1; j >= 0; j--) {
            if (Mhi[j] == bv) bk = 2 * j + 1;
            if (Mlo[j] == bv) bk = 2 * j;
        }

        // gl = local point index = bk*256 + t (monotone in global index)
        unsigned gl = (bb == wmax) ? (((unsigned)bk << 8) + (unsigned)t) : 0xffffffffu;
        const unsigned gmin = __reduce_min_sync(0xffffffffu, gl);

        const unsigned tv = (wmax >= 0) ? ((unsigned)wmax | 0x80000000u) : ~(unsigned)wmax;
        const u64t wkey = ((u64t)tv << 32) | (u64t)(0xffffffffu - (unsigned)(base + (int)gmin));

        // winner lane writes its own key + coords
        if (gl == gmin) {
            const int jj = bk >> 1;
            const bool hi = bk & 1;
            const float sx = hi ? phi(Xp[jj]) : plo(Xp[jj]);
            const float sy = hi ? phi(Yp[jj]) : plo(Yp[jj]);
            const float sz = hi ? phi(Zp[jj]) : plo(Zp[jj]);
            s_wk[warp] = wkey;
            s_wxy[warp] = pk2(sx, sy);
            s_wz[warp] = sz;
        }
        __syncthreads();

        // warps 0..3 each combine the 8 warp winners and push to rank=warp
        if (warp < CLU) {
            const u64t k = s_wk[lane & (NW - 1)];     // duplicated 4x; max unchanged
            const unsigned tvp = (unsigned)(k >> 32);
            const unsigned lowp = (unsigned)k;
            const unsigned tmax = __reduce_max_sync(0xffffffffu, tvp);
            const unsigned lw = (tvp == tmax) ? lowp : 0u;
            const unsigned lmax = __reduce_max_sync(0xffffffffu, lw);
            const u64t m = ((u64t)tmax << 32) | (u64t)lmax;
            const unsigned ball = __ballot_sync(0xffffffffu, (tvp == tmax) && (lowp == lmax));
            const int srcw = __ffs(ball) - 1;         // < NW (first duplicate)
            if (lane == 0) {
                const u64t xy = s_wxy[srcw];
                const float z = s_wz[srcw];
                const uint32_t off16 = (uint32_t)(q * CLU + r) * 16;
                const uint32_t off4  = (uint32_t)(q * CLU + r) * 4;
                st_clu_u64(a_pack + off16, (uint32_t)warp, m);
                st_clu_u64(a_pack + off16 + 8, (uint32_t)warp, xy);
                st_clu_f32(a_sz + off4, (uint32_t)warp, z);
                mbar_arrive_rel_cluster(a_bar + (uint32_t)q * 8, (uint32_t)warp);
            }
        }

        // warp0 alone waits for the 4 rank pushes, picks winner, broadcasts
        if (warp == 0) {
            if (q) { mbar_wait_acq_cluster(a_bar + 8, ph1); ph1 ^= 1u; }
            else   { mbar_wait_acq_cluster(a_bar, ph0); ph0 ^= 1u; }

            if (lane == 0) {
                const ulonglong2* pk = &s_pack[q][0];
                u64t km = pk[0].x;
                int w = 0;
                #pragma unroll
                for (int i = 1; i < CLU; i++) {
                    const u64t ki = pk[i].x;
                    if (ki > km) { km = ki; w = i; }
                }
                const u64t wxy = pk[w].y;
                const float wx = plo(wxy), wy = phi(wxy), wz = s_sz[q][w];
                s_c[0] = wx; s_c[1] = wy; s_c[2] = wz;
                if (r == 0) {
                    s_centers[s * 3 + 0] = wx;
                    s_centers[s * 3 + 1] = wy;
                    s_centers[s * 3 + 2] = wz;
                }
            }
        }
        __syncthreads();
        cx = s_c[0]; cy = s_c[1]; cz = s_c[2];
    }

    cluster_sync_();
    if (r != 0) return;

    for (int i = t; i < Gg * 3; i += FT) {
        float v = s_centers[i];
        g_centers[(size_t)b * Gg * 3 + i] = v;
        out[OUT_CENTERS + (size_t)b * Gg * 3 + i] = v;
    }

    // Greedy cluster-NMS in FPS order (warp 0)
    if (t < 32) {
        float kx[4], ky[4], kz[4];
        bool kp[4];
        #pragma unroll
        for (int qq = 0; qq < 4; qq++) {
            const int i = lane + qq * 32;
            kx[qq] = s_centers[i * 3 + 0];
            ky[qq] = s_centers[i * 3 + 1];
            kz[qq] = s_centers[i * 3 + 2];
            kp[qq] = false;
        }
        for (int j = 0; j < Gg; j++) {
            const float jx = s_centers[j * 3 + 0];
            const float jy = s_centers[j * 3 + 1];
            const float jz = s_centers[j * 3 + 2];
            bool conflict = false;
            #pragma unroll
            for (int qq = 0; qq < 4; qq++) {
                float dx = kx[qq] - jx, dy = ky[qq] - jy, dz = kz[qq] - jz;
                float d2 = dx * dx + dy * dy + dz * dz;
                if (kp[qq] && d2 < THR_F) conflict = true;
            }
            conflict = __any_sync(0xffffffffu, conflict);
            if (!conflict && lane == (j & 31)) kp[j >> 5] = true;
        }
        #pragma unroll
        for (int qq = 0; qq < 4; qq++) g_retain[b * Gg + lane + qq * 32] = kp[qq] ? 1 : 0;
    }
}

// ---------------------------------------------------------------------------
// Kernel 2: per-(group,batch) grid-culled ball query + top-32 + output
// ---------------------------------------------------------------------------
__global__ __launch_bounds__(GQ_T) void group_kernel(const float4* __restrict__ pts,
                                                     const int* __restrict__ lengths,
                                                     float* __restrict__ out) {
    const int g = blockIdx.x, b = blockIdx.y;
    const float* __restrict__ pf = (const float*)(pts + (size_t)b * Nn);
    const int t = threadIdx.x;
    const int len = lengths[b];

    const float cx = g_centers[((size_t)b * Gg + g) * 3 + 0];
    const float cy = g_centers[((size_t)b * Gg + g) * 3 + 1];
    const float cz = g_centers[((size_t)b * Gg + g) * 3 + 2];
    const int retain = g_retain[b * Gg + g];

    __shared__ int  s_segS[64];
    __shared__ int  s_segE[64];
    __shared__ u64t s_keys[256];
    __shared__ int  s_n;
    __shared__ int  s_tidx[GS];

    if (t == 0) s_n = 0;
    s_keys[t] = 0ull;
    s_keys[t + GQ_T] = 0ull;

    int lox = (int)floorf((cx - RADIUS_F) * 10.0f - 1e-4f); lox = lox < 0 ? 0 : lox;
    int hix = (int)floorf((cx + RADIUS_F) * 10.0f + 1e-4f); hix = hix > 9 ? 9 : hix;
    int loy = (int)floorf((cy - RADIUS_F) * 10.0f - 1e-4f); loy = loy < 0 ? 0 : loy;
    int hiy = (int)floorf((cy + RADIUS_F) * 10.0f + 1e-4f); hiy = hiy > 9 ? 9 : hiy;
    int loz = (int)floorf((cz - RADIUS_F) * 10.0f - 1e-4f); loz = loz < 0 ? 0 : loz;
    int hiz = (int)floorf((cz + RADIUS_F) * 10.0f + 1e-4f); hiz = hiz > 9 ? 9 : hiz;
    const int nx = hix - lox + 1, ny = hiy - loy + 1, nz = hiz - loz + 1;
    int nTot = retain ? (nx * ny * nz) : 0;

    int segCnt = 0;
    if (t < 64 && t < nTot) {
        const int ix = t % nx;
        const int iy = (t / nx) % ny;
        const int iz = t / (nx * ny);
        const int cell = ((loz + iz) * 10 + (loy + iy)) * 10 + (lox + ix);
        const int st = g_cellStart[b * (NCELL + 1) + cell];
        const int en = g_cellStart[b * (NCELL + 1) + cell + 1];
        s_segS[t] = st;
        segCnt = en - st;
    }
    if (t < 64) s_segE[t] = segCnt;
    __syncthreads();
    #pragma unroll
    for (int off = 1; off < 64; off <<= 1) {
        int x = (t >= off && t < 64) ? s_segE[t - off] : 0;
        __syncthreads();
        if (t < 64) s_segE[t] += x;
        __syncthreads();
    }
    const int C = (nTot > 0) ? s_segE[nTot - 1] : 0;
    if (t < 64) s_segE[t] -= segCnt;
    __syncthreads();

    const float4* __restrict__ bp = g_bpts + (size_t)b * Nn;
    const int* __restrict__ bi = g_bidx + (size_t)b * Nn;
    for (int pos = t; pos < C; pos += GQ_T) {
        int lo = 0, hi2 = nTot - 1;
        while (lo < hi2) {
            const int mid = (lo + hi2 + 1) >> 1;
            if (s_segE[mid] <= pos) lo = mid; else hi2 = mid - 1;
        }
        const int gp = s_segS[lo] + (pos - s_segE[lo]);
        float4 v = __ldg(bp + gp);
        const int idx = __ldg(bi + gp);
        const float dx = v.x - cx, dy = v.y - cy, dz = v.z - cz;
        const float d2 = dx * dx + dy * dy + dz * dz;
        if (d2 <= R2_F && idx < len) {
            const unsigned eb = __float_as_uint(v.w);
            const unsigned vb = (eb & 0x80000000u) ? ~eb : (eb | 0x80000000u);
            const int slot = atomicAdd(&s_n, 1);
            if (slot < 256)
                s_keys[slot] = ((u64t)vb << 32) | (u64t)(0xffffffffu - (unsigned)idx);
        }
    }
    __syncthreads();

    const int total = s_n;

    // cold path (never on this dataset): order by index, keep first UK
    if (total > UK) {
        #pragma unroll
        for (int k = 2; k <= 256; k <<= 1) {
            #pragma unroll
            for (int j = k >> 1; j > 0; j >>= 1) {
                #pragma unroll
                for (int e = 0; e < 2; e++) {
                    const int i = t + e * GQ_T;
                    const int l = i ^ j;
                    if (l > i) {
                        const u64t a = s_keys[i], c = s_keys[l];
                        const unsigned la = (unsigned)a, lc = (unsigned)c;
                        const bool up = ((i & k) == 0);
                        if (up ? (la < lc) : (la > lc)) { s_keys[i] = c; s_keys[l] = a; }
                    }
                }
                __syncthreads();
            }
        }
    }
    __syncthreads();

    const int numEff = total < UK ? total : UK;

    if (t < 32) {
        u64t key[4];
        #pragma unroll
        for (int rr = 0; rr < 4; rr++) {
            const int slot = rr * 32 + t;
            key[rr] = (slot < numEff) ? s_keys[slot] : 0ull;
        }
        #pragma unroll
        for (int k = 2; k <= 128; k <<= 1) {
            #pragma unroll
            for (int j = k >> 1; j > 0; j >>= 1) {
                if (j >= 32) {
                    const int rj = j >> 5;
                    #pragma unroll
                    for (int rr = 0; rr < 4; rr++) {
                        const int pr = rr ^ rj;
                        if (pr > rr) {
                            const int e = rr * 32 + t;
                            const bool dsc = ((e & k) == 0);
                            u64t a = key[rr], c = key[pr];
                            u64t mx = a > c ? a : c;
                            u64t mn = a > c ? c : a;
                            key[rr] = dsc ? mx : mn;
                            key[pr] = dsc ? mn : mx;
                        }
                    }
                } else {
                    #pragma unroll
                    for (int rr = 0; rr < 4; rr++) {
                        const int e = rr * 32 + t;
                        u64t o = __shfl_xor_sync(0xffffffffu, key[rr], j);
                        const bool low = ((t & j) == 0);
                        const bool dsc = ((e & k) == 0);
                        const bool takeMax = (dsc == low);
                        u64t mx = key[rr] > o ? key[rr] : o;
                        u64t mn = key[rr] > o ? o : key[rr];
                        key[rr] = takeMax ? mx : mn;
                    }
                }
            }
        }
        const u64t k0 = key[0];
        const int idx = (int)(0xffffffffu - (unsigned)k0);
        s_tidx[t] = ((unsigned)(k0 >> 32) >= 0x80000000u) ? idx : -1;
    }
    __syncthreads();

    {
        const int rr = t >> 2, c = t & 3;
        const int ti = s_tidx[rr];
        const int fi = (ti == -1) ? s_tidx[0] : ti;
        float val = (fi == -1) ? 0.0f : pf[(size_t)fi * 4 + c];
        if (c < 3) {
            const float cc = (c == 0) ? cx : (c == 1) ? cy : cz;
            val -= cc;
        }
        val = __fdiv_rn(val, RADIUS_F);
        out[OUT_GROUPS + ((((size_t)b * Gg + g) * GS) + rr) * Cc + c] = val;
    }
    if (t == 0 && total >= GS) atomicAdd(&g_glen[b], 1);
}

// ---------------------------------------------------------------------------
// Kernel 3: embedding mask
// ---------------------------------------------------------------------------
__global__ void mask_kernel(float* __restrict__ out) {
    const int i = blockIdx.x * blockDim.x + threadIdx.x;
    if (i < Bn * Gg) {
        const int b = i >> 7, g = i & (Gg - 1);
        out[OUT_MASK + i] = (g < g_glen[b]) ? 1.0f : 0.0f;
    }
}

extern "C" void kernel_launch(void* const* d_in, const int* in_sizes, int n_in,
                              void* d_out, int out_size) {
    const float4* pts = (const float4*)d_in[0];
    const int* lengths = (const int*)d_in[1];
    float* out = (float*)d_out;
    (void)in_sizes; (void)n_in; (void)out_size;

    fps_kernel<<<Bn * CLU + Bn, FT>>>(pts, lengths, out);
    group_kernel<<<dim3(Gg, Bn), GQ_T>>>(pts, lengths, out);
    mask_kernel<<<(Bn * Gg + 255) / 256, 256>>>(out);
}

// round 17
// speedup vs baseline: 2.5457x; 1.0566x over previous
#include <cuda_runtime.h>
#include <cuda_bf16.h>
#include <cstdint>

// Problem constants
#define Bn 8
#define Nn 16384
#define Cc 4
#define Gg 128          // NUM_GROUPS
#define GS 32           // GROUP_SIZE
#define UK 128          // UPSCALE_K
#define CLU 8           // cluster size for FPS
#define FT 256          // threads per CTA (fps + bin)
#define NW (FT / 32)    // 8 warps
#define PPC (Nn / CLU)  // 2048 points per FPS CTA
#define FPAIR (PPC / FT / 2)   // 4 packed pairs (8 pts) per thread
#define GQ_T 128        // group kernel threads
#define NCELL 1000      // 10x10x10 grid

typedef unsigned long long u64t;

__device__ __forceinline__ float NEG_INF() { return __int_as_float(0xff800000); }
__device__ __forceinline__ float POS_INF() { return __int_as_float(0x7f800000); }
#define RADIUS_F 0.1f
#define R2_F 0.01f                  // f32(0.01)
#define THR_F 0.0036f               // f32((2*0.1*0.3)^2)

// Output layout: groups | centers | mask
#define OUT_GROUPS 0
#define OUT_CENTERS (Bn * Gg * GS * Cc)          // 131072
#define OUT_MASK (OUT_CENTERS + Bn * Gg * 3)     // 134144

__device__ float  g_centers[Bn * Gg * 3];
__device__ int    g_retain[Bn * Gg];
__device__ int    g_glen[Bn];
__device__ int    g_cellStart[Bn * (NCELL + 1)];
__device__ float4 g_bpts[Bn * Nn];
__device__ int    g_bidx[Bn * Nn];

// ---- f32x2 packed helpers (sm_100+) ----
__device__ __forceinline__ u64t pk2(float lo, float hi) {
    u64t r; asm("mov.b64 %0, {%1, %2};" : "=l"(r) : "f"(lo), "f"(hi)); return r;
}
__device__ __forceinline__ float plo(u64t v) { return __uint_as_float((unsigned)v); }
__device__ __forceinline__ float phi(u64t v) { return __uint_as_float((unsigned)(v >> 32)); }
__device__ __forceinline__ u64t add2(u64t a, u64t b) {
    u64t r; asm("add.rn.f32x2 %0, %1, %2;" : "=l"(r) : "l"(a), "l"(b)); return r;
}
__device__ __forceinline__ u64t mul2(u64t a, u64t b) {
    u64t r; asm("mul.rn.f32x2 %0, %1, %2;" : "=l"(r) : "l"(a), "l"(b)); return r;
}
__device__ __forceinline__ u64t fma2(u64t a, u64t b, u64t c) {
    u64t r; asm("fma.rn.f32x2 %0, %1, %2, %3;" : "=l"(r) : "l"(a), "l"(b), "l"(c)); return r;
}

// ---- cluster helpers ----
__device__ __forceinline__ uint32_t smem_u32(const void* p) {
    uint32_t a;
    asm("{ .reg .u64 t; cvta.to.shared.u64 t, %1; cvt.u32.u64 %0, t; }" : "=r"(a) : "l"(p));
    return a;
}
__device__ __forceinline__ void st_clu_u64(uint32_t laddr, uint32_t rank, u64t v) {
    uint32_t ra;
    asm("mapa.shared::cluster.u32 %0, %1, %2;" : "=r"(ra) : "r"(laddr), "r"(rank));
    asm volatile("st.shared::cluster.u64 [%0], %1;" :: "r"(ra), "l"(v) : "memory");
}
__device__ __forceinline__ void st_clu_f32(uint32_t laddr, uint32_t rank, float v) {
    uint32_t ra;
    asm("mapa.shared::cluster.u32 %0, %1, %2;" : "=r"(ra) : "r"(laddr), "r"(rank));
    asm volatile("st.shared::cluster.f32 [%0], %1;" :: "r"(ra), "f"(v) : "memory");
}
__device__ __forceinline__ void mbar_init(uint32_t addr, uint32_t count) {
    asm volatile("mbarrier.init.shared.b64 [%0], %1;" :: "r"(addr), "r"(count) : "memory");
}
__device__ __forceinline__ void mbar_arrive_rel_cluster(uint32_t laddr, uint32_t rank) {
    uint32_t ra;
    asm("mapa.shared::cluster.u32 %0, %1, %2;" : "=r"(ra) : "r"(laddr), "r"(rank));
    asm volatile("mbarrier.arrive.release.cluster.shared::cluster.b64 _, [%0];"
                 :: "r"(ra) : "memory");
}
__device__ __forceinline__ void mbar_wait_acq_cluster(uint32_t addr, uint32_t parity) {
    asm volatile(
        "{\n\t.reg .pred P;\n\t"
        "WL_%=:\n\t"
        "mbarrier.try_wait.parity.acquire.cluster.shared::cta.b64 P, [%0], %1, 0x989680;\n\t"
        "@P bra.uni WD_%=;\n\t"
        "bra.uni WL_%=;\n\t"
        "WD_%=:\n\t}"
        :: "r"(addr), "r"(parity) : "memory");
}
__device__ __forceinline__ void cluster_sync_() {
    asm volatile("barrier.cluster.arrive.aligned;" ::: "memory");
    asm volatile("barrier.cluster.wait.aligned;" ::: "memory");
}

__device__ __forceinline__ int cell_of(float x, float y, float z) {
    int cx = (int)(x * 10.0f); cx = cx < 0 ? 0 : (cx > 9 ? 9 : cx);
    int cy = (int)(y * 10.0f); cy = cy < 0 ? 0 : (cy > 9 ? 9 : cy);
    int cz = (int)(z * 10.0f); cz = cz < 0 ? 0 : (cz > 9 ? 9 : cz);
    return (cz * 10 + cy) * 10 + cx;
}

// ---------------------------------------------------------------------------
// Kernel 1: blocks [0, Bn*CLU): cluster-parallel FPS (8 CTAs/batch, 256 thr)
//           blocks [Bn*CLU, Bn*CLU+Bn): per-batch grid binning (overlapped)
// ---------------------------------------------------------------------------
__global__ __launch_bounds__(FT) __cluster_dims__(CLU, 1, 1)
void fps_kernel(const float4* __restrict__ pts,
                const int* __restrict__ lengths,
                float* __restrict__ out) {
    const int bid = blockIdx.x;
    const int t = threadIdx.x;
    const int lane = t & 31, warp = t >> 5;

    if (bid >= Bn * CLU) {
        // ---------------- binning path (256 threads) ----------------
        const int b = bid - Bn * CLU;
        const float4* __restrict__ p = pts + (size_t)b * Nn;
        __shared__ int s_cnt[NCELL];
        __shared__ int s_ws[NW];

        for (int i = t; i < NCELL; i += FT) s_cnt[i] = 0;
        __syncthreads();

        for (int k = 0; k < Nn / FT; k++) {
            const int i = t + k * FT;
            float4 v = __ldg(p + i);
            atomicAdd(&s_cnt[cell_of(v.x, v.y, v.z)], 1);
        }
        __syncthreads();

        // scan: thread t owns cells [4t, 4t+4)
        int c4[4];
        int T = 0;
        #pragma unroll
        for (int j = 0; j < 4; j++) {
            const int i = 4 * t + j;
            c4[j] = (i < NCELL) ? s_cnt[i] : 0;
            T += c4[j];
        }
        int v = T;
        #pragma unroll
        for (int off = 1; off < 32; off <<= 1) {
            int o = __shfl_up_sync(0xffffffffu, v, off);
            if (lane >= off) v += o;
        }
        if (lane == 31) s_ws[warp] = v;
        __syncthreads();
        if (t < NW) {
            int w = s_ws[t];
            #pragma unroll
            for (int off = 1; off < NW; off <<= 1) {
                int o = __shfl_up_sync((1u << NW) - 1u, w, off);
                if (t >= off) w += o;
            }
            s_ws[t] = w;
        }
        __syncthreads();
        int run = ((warp == 0) ? 0 : s_ws[warp - 1]) + v - T;
        int ex4[4];
        #pragma unroll
        for (int j = 0; j < 4; j++) { ex4[j] = run; run += c4[j]; }
        __syncthreads();
        #pragma unroll
        for (int j = 0; j < 4; j++) {
            const int i = 4 * t + j;
            if (i < NCELL) {
                g_cellStart[b * (NCELL + 1) + i] = ex4[j];
                s_cnt[i] = ex4[j];
            }
        }
        if (t == 0) g_cellStart[b * (NCELL + 1) + NCELL] = Nn;
        __syncthreads();

        for (int k = 0; k < Nn / FT; k++) {
            const int i = t + k * FT;
            float4 vv = __ldg(p + i);
            const int c = cell_of(vv.x, vv.y, vv.z);
            const int pos = atomicAdd(&s_cnt[c], 1);
            g_bpts[(size_t)b * Nn + pos] = vv;
            g_bidx[(size_t)b * Nn + pos] = i;
        }
        return;
    }

    // ---------------- FPS path ----------------
    const int b = bid / CLU;
    const int r = bid % CLU;
    const float4* __restrict__ p = pts + (size_t)b * Nn;
    const int len = lengths[b];
    const int base = r * PPC;

    __shared__ u64t  s_wk[NW];
    __shared__ u64t  s_wxy[NW];
    __shared__ float s_wz[NW];
    __shared__ __align__(16) ulonglong2 s_pack[2][CLU];   // {key, xy} per rank
    __shared__ float s_sz[2][CLU];
    __shared__ float s_c[3];
    __shared__ __align__(8) unsigned char s_bar[2][8];
    __shared__ float s_centers[Gg * 3];

    const uint32_t a_pack = smem_u32(&s_pack[0][0]);
    const uint32_t a_sz   = smem_u32(&s_sz[0][0]);
    const uint32_t a_bar  = smem_u32(&s_bar[0][0]);

    if (t == 0) {
        mbar_init(a_bar, CLU);
        mbar_init(a_bar + 8, CLU);
        if (r == 0) g_glen[b] = 0;
    }

    // 8 pts/thread as 4 pairs: pair j = local idx (t + 2j*256, t + (2j+1)*256)
    u64t Xp[FPAIR], Yp[FPAIR], Zp[FPAIR];
    float Mlo[FPAIR], Mhi[FPAIR];
    #pragma unroll
    for (int j = 0; j < FPAIR; j++) {
        const int i0 = base + t + (2 * j) * FT;
        const int i1 = i0 + FT;
        float4 a = __ldg(p + i0);
        float4 c = __ldg(p + i1);
        Xp[j] = pk2(a.x, c.x);
        Yp[j] = pk2(a.y, c.y);
        Zp[j] = pk2(a.z, c.z);
        Mlo[j] = (i0 < len) ? POS_INF() : NEG_INF();
        Mhi[j] = (i1 < len) ? POS_INF() : NEG_INF();
    }

    float4 c0 = __ldg(p);
    float cx = c0.x, cy = c0.y, cz = c0.z;
    if (r == 0 && t == 0) {
        s_centers[0] = cx; s_centers[1] = cy; s_centers[2] = cz;
    }

    // barriers must be cluster-visible before any remote arrive
    __syncthreads();
    cluster_sync_();

    unsigned ph0 = 0, ph1 = 0;

    for (int s = 1; s < Gg; s++) {
        const int q = s & 1;
        const u64t ncx = pk2(-cx, -cx);
        const u64t ncy = pk2(-cy, -cy);
        const u64t ncz = pk2(-cz, -cz);

        #pragma unroll
        for (int j = 0; j < FPAIR; j++) {
            u64t dx = add2(Xp[j], ncx);
            u64t dy = add2(Yp[j], ncy);
            u64t dz = add2(Zp[j], ncz);
            u64t d = mul2(dx, dx);
            d = fma2(dy, dy, d);
            d = fma2(dz, dz, d);
            Mlo[j] = fminf(Mlo[j], plo(d));
            Mhi[j] = fminf(Mhi[j], phi(d));
        }

        // thread-local max over 8 mins
        float bv = NEG_INF();
        #pragma unroll
        for (int j = 0; j < FPAIR; j++) bv = fmaxf(bv, fmaxf(Mlo[j], Mhi[j]));

        const int bb = __float_as_int(bv);
        const int wmax = __reduce_max_sync(0xffffffffu, bb);

        // min local slot k (0..7) matching bv
        int bk = 2 * FPAIR - 1;
        #pragma unroll
        for (int j = FPAIR - 1; j >= 0; j--) {
            if (Mhi[j] == bv) bk = 2 * j + 1;
            if (Mlo[j] == bv) bk = 2 * j;
        }

        // gl = local point index = bk*256 + t
        unsigned gl = (bb == wmax) ? (((unsigned)bk << 8) + (unsigned)t) : 0xffffffffu;
        const unsigned gmin = __reduce_min_sync(0xffffffffu, gl);

        const unsigned tv = (wmax >= 0) ? ((unsigned)wmax | 0x80000000u) : ~(unsigned)wmax;
        const u64t wkey = ((u64t)tv << 32) | (u64t)(0xffffffffu - (unsigned)(base + (int)gmin));

        // winner lane writes its own key + coords
        if (gl == gmin) {
            const int jj = bk >> 1;
            const bool hi = bk & 1;
            const float sx = hi ? phi(Xp[jj]) : plo(Xp[jj]);
            const float sy = hi ? phi(Yp[jj]) : plo(Yp[jj]);
            const float sz = hi ? phi(Zp[jj]) : plo(Zp[jj]);
            s_wk[warp] = wkey;
            s_wxy[warp] = pk2(sx, sy);
            s_wz[warp] = sz;
        }
        __syncthreads();

        // all 8 warps each combine the 8 warp winners and push to rank=warp
        {
            const u64t k = s_wk[lane & (NW - 1)];     // duplicated 4x; max unchanged
            const unsigned tvp = (unsigned)(k >> 32);
            const unsigned lowp = (unsigned)k;
            const unsigned tmax = __reduce_max_sync(0xffffffffu, tvp);
            const unsigned lw = (tvp == tmax) ? lowp : 0u;
            const unsigned lmax = __reduce_max_sync(0xffffffffu, lw);
            const u64t m = ((u64t)tmax << 32) | (u64t)lmax;
            const unsigned ball = __ballot_sync(0xffffffffu, (tvp == tmax) && (lowp == lmax));
            const int srcw = __ffs(ball) - 1;         // < NW (first duplicate)
            if (lane == 0) {
                const u64t xy = s_wxy[srcw];
                const float z = s_wz[srcw];
                const uint32_t off16 = (uint32_t)(q * CLU + r) * 16;
                const uint32_t off4  = (uint32_t)(q * CLU + r) * 4;
                st_clu_u64(a_pack + off16, (uint32_t)warp, m);
                st_clu_u64(a_pack + off16 + 8, (uint32_t)warp, xy);
                st_clu_f32(a_sz + off4, (uint32_t)warp, z);
                mbar_arrive_rel_cluster(a_bar + (uint32_t)q * 8, (uint32_t)warp);
            }
        }

        // warp0 alone waits for the 8 rank pushes, picks winner (parallel redux)
        if (warp == 0) {
            if (q) { mbar_wait_acq_cluster(a_bar + 8, ph1); ph1 ^= 1u; }
            else   { mbar_wait_acq_cluster(a_bar, ph0); ph0 ^= 1u; }

            const ulonglong2 pe = s_pack[q][lane & (CLU - 1)];
            const float pz = s_sz[q][lane & (CLU - 1)];
            const unsigned hi = (unsigned)(pe.x >> 32);
            const unsigned lo = (unsigned)pe.x;
            const unsigned hmax = __reduce_max_sync(0xffffffffu, hi);
            const unsigned lw2 = (hi == hmax) ? lo : 0u;
            const unsigned lmax2 = __reduce_max_sync(0xffffffffu, lw2);
            const unsigned ball2 = __ballot_sync(0xffffffffu, (hi == hmax) && (lo == lmax2));
            const int srcs = __ffs(ball2) - 1;
            const u64t wxy = __shfl_sync(0xffffffffu, pe.y, srcs);
            const float wz = __shfl_sync(0xffffffffu, pz, srcs);
            if (lane == 0) {
                const float wx = plo(wxy), wy = phi(wxy);
                s_c[0] = wx; s_c[1] = wy; s_c[2] = wz;
                if (r == 0) {
                    s_centers[s * 3 + 0] = wx;
                    s_centers[s * 3 + 1] = wy;
                    s_centers[s * 3 + 2] = wz;
                }
            }
        }
        __syncthreads();
        cx = s_c[0]; cy = s_c[1]; cz = s_c[2];
    }

    cluster_sync_();
    if (r != 0) return;

    for (int i = t; i < Gg * 3; i += FT) {
        float v = s_centers[i];
        g_centers[(size_t)b * Gg * 3 + i] = v;
        out[OUT_CENTERS + (size_t)b * Gg * 3 + i] = v;
    }

    // Greedy cluster-NMS in FPS order (warp 0)
    if (t < 32) {
        float kx[4], ky[4], kz[4];
        bool kp[4];
        #pragma unroll
        for (int qq = 0; qq < 4; qq++) {
            const int i = lane + qq * 32;
            kx[qq] = s_centers[i * 3 + 0];
            ky[qq] = s_centers[i * 3 + 1];
            kz[qq] = s_centers[i * 3 + 2];
            kp[qq] = false;
        }
        for (int j = 0; j < Gg; j++) {
            const float jx = s_centers[j * 3 + 0];
            const float jy = s_centers[j * 3 + 1];
            const float jz = s_centers[j * 3 + 2];
            bool conflict = false;
            #pragma unroll
            for (int qq = 0; qq < 4; qq++) {
                float dx = kx[qq] - jx, dy = ky[qq] - jy, dz = kz[qq] - jz;
                float d2 = dx * dx + dy * dy + dz * dz;
                if (kp[qq] && d2 < THR_F) conflict = true;
            }
            conflict = __any_sync(0xffffffffu, conflict);
            if (!conflict && lane == (j & 31)) kp[j >> 5] = true;
        }
        #pragma unroll
        for (int qq = 0; qq < 4; qq++) g_retain[b * Gg + lane + qq * 32] = kp[qq] ? 1 : 0;
    }
}

// ---------------------------------------------------------------------------
// Kernel 2: per-(group,batch) grid-culled ball query + top-32 + output
// ---------------------------------------------------------------------------
__global__ __launch_bounds__(GQ_T) void group_kernel(const float4* __restrict__ pts,
                                                     const int* __restrict__ lengths,
                                                     float* __restrict__ out) {
    const int g = blockIdx.x, b = blockIdx.y;
    const float* __restrict__ pf = (const float*)(pts + (size_t)b * Nn);
    const int t = threadIdx.x;
    const int len = lengths[b];

    const float cx = g_centers[((size_t)b * Gg + g) * 3 + 0];
    const float cy = g_centers[((size_t)b * Gg + g) * 3 + 1];
    const float cz = g_centers[((size_t)b * Gg + g) * 3 + 2];
    const int retain = g_retain[b * Gg + g];

    __shared__ int  s_segS[64];
    __shared__ int  s_segE[64];    // exclusive prefix after warp0 scan
    __shared__ int  s_C;
    __shared__ u64t s_keys[256];
    __shared__ int  s_n;
    __shared__ int  s_tidx[GS];

    if (t == 0) s_n = 0;
    s_keys[t] = 0ull;
    s_keys[t + GQ_T] = 0ull;

    int lox = (int)floorf((cx - RADIUS_F) * 10.0f - 1e-4f); lox = lox < 0 ? 0 : lox;
    int hix = (int)floorf((cx + RADIUS_F) * 10.0f + 1e-4f); hix = hix > 9 ? 9 : hix;
    int loy = (int)floorf((cy - RADIUS_F) * 10.0f - 1e-4f); loy = loy < 0 ? 0 : loy;
    int hiy = (int)floorf((cy + RADIUS_F) * 10.0f + 1e-4f); hiy = hiy > 9 ? 9 : hiy;
    int loz = (int)floorf((cz - RADIUS_F) * 10.0f - 1e-4f); loz = loz < 0 ? 0 : loz;
    int hiz = (int)floorf((cz + RADIUS_F) * 10.0f + 1e-4f); hiz = hiz > 9 ? 9 : hiz;
    const int nx = hix - lox + 1, ny = hiy - loy + 1, nz = hiz - loz + 1;
    int nTot = retain ? (nx * ny * nz) : 0;

    int segCnt = 0;
    if (t < 64 && t < nTot) {
        const int ix = t % nx;
        const int iy = (t / nx) % ny;
        const int iz = t / (nx * ny);
        const int cell = ((loz + iz) * 10 + (loy + iy)) * 10 + (lox + ix);
        const int st = g_cellStart[b * (NCELL + 1) + cell];
        const int en = g_cellStart[b * (NCELL + 1) + cell + 1];
        s_segS[t] = st;
        segCnt = en - st;
    }
    if (t < 64) s_segE[t] = segCnt;
    __syncthreads();

    // warp0: exclusive scan of 64 counts (2 elems/lane), one barrier
    if (t < 32) {
        const int e0 = s_segE[2 * t];
        const int e1 = s_segE[2 * t + 1];
        const int sum = e0 + e1;
        int v = sum;
        #pragma unroll
        for (int off = 1; off < 32; off <<= 1) {
            int o = __shfl_up_sync(0xffffffffu, v, off);
            if (t >= off) v += o;
        }
        const int excl = v - sum;
        s_segE[2 * t] = excl;
        s_segE[2 * t + 1] = excl + e0;
        if (t == 31) s_C = v;
    }
    __syncthreads();

    const int C = (nTot > 0) ? s_C : 0;

    const float4* __restrict__ bp = g_bpts + (size_t)b * Nn;
    const int* __restrict__ bi = g_bidx + (size_t)b * Nn;
    for (int pos = t; pos < C; pos += GQ_T) {
        int lo = 0, hi2 = nTot - 1;
        while (lo < hi2) {
            const int mid = (lo + hi2 + 1) >> 1;
            if (s_segE[mid] <= pos) lo = mid; else hi2 = mid - 1;
        }
        const int gp = s_segS[lo] + (pos - s_segE[lo]);
        float4 v = __ldg(bp + gp);
        const int idx = __ldg(bi + gp);
        const float dx = v.x - cx, dy = v.y - cy, dz = v.z - cz;
        const float d2 = dx * dx + dy * dy + dz * dz;
        if (d2 <= R2_F && idx < len) {
            const unsigned eb = __float_as_uint(v.w);
            const unsigned vb = (eb & 0x80000000u) ? ~eb : (eb | 0x80000000u);
            const int slot = atomicAdd(&s_n, 1);
            if (slot < 256)
                s_keys[slot] = ((u64t)vb << 32) | (u64t)(0xffffffffu - (unsigned)idx);
        }
    }
    __syncthreads();

    const int total = s_n;

    // cold path (never on this dataset): order by index, keep first UK
    if (total > UK) {
        #pragma unroll
        for (int k = 2; k <= 256; k <<= 1) {
            #pragma unroll
            for (int j = k >> 1; j > 0; j >>= 1) {
                #pragma unroll
                for (int e = 0; e < 2; e++) {
                    const int i = t + e * GQ_T;
                    const int l = i ^ j;
                    if (l > i) {
                        const u64t a = s_keys[i], c = s_keys[l];
                        const unsigned la = (unsigned)a, lc = (unsigned)c;
                        const bool up = ((i & k) == 0);
                        if (up ? (la < lc) : (la > lc)) { s_keys[i] = c; s_keys[l] = a; }
                    }
                }
                __syncthreads();
            }
        }
    }
    __syncthreads();

    const int numEff = total < UK ? total : UK;

    if (t < 32) {
        u64t key[4];
        #pragma unroll
        for (int rr = 0; rr < 4; rr++) {
            const int slot = rr * 32 + t;
            key[rr] = (slot < numEff) ? s_keys[slot] : 0ull;
        }
        #pragma unroll
        for (int k = 2; k <= 128; k <<= 1) {
            #pragma unroll
            for (int j = k >> 1; j > 0; j >>= 1) {
                if (j >= 32) {
                    const int rj = j >> 5;
                    #pragma unroll
                    for (int rr = 0; rr < 4; rr++) {
                        const int pr = rr ^ rj;
                        if (pr > rr) {
                            const int e = rr * 32 + t;
                            const bool dsc = ((e & k) == 0);
                            u64t a = key[rr], c = key[pr];
                            u64t mx = a > c ? a : c;
                            u64t mn = a > c ? c : a;
                            key[rr] = dsc ? mx : mn;
                            key[pr] = dsc ? mn : mx;
                        }
                    }
                } else {
                    #pragma unroll
                    for (int rr = 0; rr < 4; rr++) {
                        const int e = rr * 32 + t;
                        u64t o = __shfl_xor_sync(0xffffffffu, key[rr], j);
                        const bool low = ((t & j) == 0);
                        const bool dsc = ((e & k) == 0);
                        const bool takeMax = (dsc == low);
                        u64t mx = key[rr] > o ? key[rr] : o;
                        u64t mn = key[rr] > o ? o : key[rr];
                        key[rr] = takeMax ? mx : mn;
                    }
                }
            }
        }
        const u64t k0 = key[0];
        const int idx = (int)(0xffffffffu - (unsigned)k0);
        s_tidx[t] = ((unsigned)(k0 >> 32) >= 0x80000000u) ? idx : -1;
    }
    __syncthreads();

    {
        const int rr = t >> 2, c = t & 3;
        const int ti = s_tidx[rr];
        const int fi = (ti == -1) ? s_tidx[0] : ti;
        float val = (fi == -1) ? 0.0f : pf[(size_t)fi * 4 + c];
        if (c < 3) {
            const float cc = (c == 0) ? cx : (c == 1) ? cy : cz;
            val -= cc;
        }
        val = __fdiv_rn(val, RADIUS_F);
        out[OUT_GROUPS + ((((size_t)b * Gg + g) * GS) + rr) * Cc + c] = val;
    }
    if (t == 0 && total >= GS) atomicAdd(&g_glen[b], 1);
}

// ---------------------------------------------------------------------------
// Kernel 3: embedding mask
// ---------------------------------------------------------------------------
__global__ void mask_kernel(float* __restrict__ out) {
    const int i = blockIdx.x * blockDim.x + threadIdx.x;
    if (i < Bn * Gg) {
        const int b = i >> 7, g = i & (Gg - 1);
        out[OUT_MASK + i] = (g < g_glen[b]) ? 1.0f : 0.0f;
    }
}

extern "C" void kernel_launch(void* const* d_in, const int* in_sizes, int n_in,
                              void* d_out, int out_size) {
    const float4* pts = (const float4*)d_in[0];
    const int* lengths = (const int*)d_in[1];
    float* out = (float*)d_out;
    (void)in_sizes; (void)n_in; (void)out_size;

    fps_kernel<<<Bn * CLU + Bn, FT>>>(pts, lengths, out);
    group_kernel<<<dim3(Gg, Bn), GQ_T>>>(pts, lengths, out);
    mask_kernel<<<(Bn * Gg + 255) / 256, 256>>>(out);
}